// round 3
// baseline (speedup 1.0000x reference)
#include <cuda_runtime.h>
#include <cuda_bf16.h>
#include <cstdint>

#define SEQ     4096
#define DMODEL  1024
#define NHEADS  16
#define DH      64
#define QKVDIM  (3 * DMODEL)

// ---------------- scratch (split bf16 hi/lo) ----------------
__device__ __nv_bfloat16 g_xh[(size_t)SEQ * DMODEL],    g_xl[(size_t)SEQ * DMODEL];
__device__ __nv_bfloat16 g_wqh[(size_t)QKVDIM * DMODEL], g_wql[(size_t)QKVDIM * DMODEL];
__device__ __nv_bfloat16 g_woh[(size_t)DMODEL * DMODEL], g_wol[(size_t)DMODEL * DMODEL];
__device__ __nv_bfloat16 g_qkvh[(size_t)SEQ * QKVDIM],  g_qkvl[(size_t)SEQ * QKVDIM];
__device__ __nv_bfloat16 g_ctxh[(size_t)SEQ * DMODEL],  g_ctxl[(size_t)SEQ * DMODEL];

// ============================================================
// helpers
// ============================================================
__device__ __forceinline__ uint32_t smaddr(const void* p) {
    return static_cast<uint32_t>(__cvta_generic_to_shared(p));
}
__device__ __forceinline__ uint32_t b2u(__nv_bfloat162 v) {
    return *reinterpret_cast<uint32_t*>(&v);
}
__device__ __forceinline__ void split2(float x, float y, uint32_t& hi, uint32_t& lo) {
    __nv_bfloat162 h = __float22bfloat162_rn(make_float2(x, y));
    float2 hf = __bfloat1622float2(h);
    __nv_bfloat162 l = __float22bfloat162_rn(make_float2(x - hf.x, y - hf.y));
    hi = b2u(h); lo = b2u(l);
}
__device__ __forceinline__ void ldsm_x4(uint32_t* r, uint32_t addr) {
    asm volatile("ldmatrix.sync.aligned.m8n8.x4.shared.b16 {%0,%1,%2,%3}, [%4];"
                 : "=r"(r[0]), "=r"(r[1]), "=r"(r[2]), "=r"(r[3]) : "r"(addr));
}
__device__ __forceinline__ void ldsm_x4_t(uint32_t* r, uint32_t addr) {
    asm volatile("ldmatrix.sync.aligned.m8n8.x4.trans.shared.b16 {%0,%1,%2,%3}, [%4];"
                 : "=r"(r[0]), "=r"(r[1]), "=r"(r[2]), "=r"(r[3]) : "r"(addr));
}
__device__ __forceinline__ void mma_bf16(float* d, const uint32_t* a, uint32_t b0, uint32_t b1) {
    asm volatile(
        "mma.sync.aligned.m16n8k16.row.col.f32.bf16.bf16.f32 "
        "{%0,%1,%2,%3}, {%4,%5,%6,%7}, {%8,%9}, {%0,%1,%2,%3};"
        : "+f"(d[0]), "+f"(d[1]), "+f"(d[2]), "+f"(d[3])
        : "r"(a[0]), "r"(a[1]), "r"(a[2]), "r"(a[3]), "r"(b0), "r"(b1));
}
#define CP16(dst, src) asm volatile("cp.async.cg.shared.global [%0], [%1], 16;" :: "r"(dst), "l"(src))
#define CP_COMMIT()    asm volatile("cp.async.commit_group;")
#define CP_WAIT1()     asm volatile("cp.async.wait_group 1;")
#define CP_WAIT0()     asm volatile("cp.async.wait_group 0;")

// ============================================================
// prepass: split fp32 -> bf16 hi/lo
// ============================================================
__global__ void split_kernel(const float* __restrict__ in,
                             __nv_bfloat16* __restrict__ h,
                             __nv_bfloat16* __restrict__ l, int n4)
{
    int i = blockIdx.x * blockDim.x + threadIdx.x;
    if (i >= n4) return;
    float4 v = ((const float4*)in)[i];
    uint32_t h0, h1, l0, l1;
    split2(v.x, v.y, h0, l0);
    split2(v.z, v.w, h1, l1);
    ((uint2*)h)[i] = make_uint2(h0, h1);
    ((uint2*)l)[i] = make_uint2(l0, l1);
}

// ============================================================
// GEMM: C[M,N] = (Ah+Al)[M,K] * (Bh+Bl)[N,K]^T + bias
// CTA 128x128, 256 thr (8 warps 2x4), warp 64x32, k-step 32,
// cp.async double buffer. SPLIT_OUT: write bf16 hi/lo, else fp32.
// ============================================================
#define KST 40   // smem row stride (bf16 elems) = 80B (conflict-free ldsm)
#define GEMM_STAGE_ELEMS (4 * 128 * KST)   // Ah,Al,Bh,Bl per stage
#define GEMM_SMEM_BYTES  (2 * GEMM_STAGE_ELEMS * 2)

template <bool SPLIT_OUT>
__global__ __launch_bounds__(256)
void gemm_split(const __nv_bfloat16* __restrict__ Ah, const __nv_bfloat16* __restrict__ Al,
                const __nv_bfloat16* __restrict__ Bh, const __nv_bfloat16* __restrict__ Bl,
                const float* __restrict__ bias,
                float* __restrict__ Cf,
                __nv_bfloat16* __restrict__ Ch, __nv_bfloat16* __restrict__ Cl,
                int M, int N, int K)
{
    extern __shared__ __nv_bfloat16 sm[];

    const int tid = threadIdx.x;
    const int w = tid >> 5, lane = tid & 31;
    const int wr = w >> 2, wc = w & 3;
    const int g = lane >> 2, tg = lane & 3;
    const int bm = blockIdx.y * 128, bn = blockIdx.x * 128;

    const uint32_t smb = smaddr(sm);

    float acc[4][4][4];
#pragma unroll
    for (int a = 0; a < 4; a++)
#pragma unroll
        for (int b = 0; b < 4; b++)
#pragma unroll
            for (int c = 0; c < 4; c++) acc[a][b][c] = 0.f;

    // cp.async tile issue: 128 rows x 4 chunks (16B) per matrix-half
    const int r0 = tid >> 1;            // rows: 2 iters cover 0..127 twice? no:
    // idx scheme: idx = tid + i*256, i in {0,1}; row = idx>>2, chunk = idx&3
    auto issue_stage = [&](int kt, int stage) {
        const size_t ko = (size_t)kt * 32;
        uint32_t base = smb + (uint32_t)stage * GEMM_STAGE_ELEMS * 2;
#pragma unroll
        for (int i = 0; i < 2; i++) {
            int idx = tid + i * 256;
            int r = idx >> 2, c = idx & 3;
            uint32_t d = base + (uint32_t)(r * KST + c * 8) * 2;
            const __nv_bfloat16* sa = Ah + (size_t)(bm + r) * K + ko + c * 8;
            CP16(d, sa);
            const __nv_bfloat16* sal = Al + (size_t)(bm + r) * K + ko + c * 8;
            CP16(d + 128 * KST * 2, sal);
            const __nv_bfloat16* sb = Bh + (size_t)(bn + r) * K + ko + c * 8;
            CP16(d + 2 * 128 * KST * 2, sb);
            const __nv_bfloat16* sbl = Bl + (size_t)(bn + r) * K + ko + c * 8;
            CP16(d + 3 * 128 * KST * 2, sbl);
        }
    };

    const int nsteps = K >> 5;
    issue_stage(0, 0);
    CP_COMMIT();

    for (int kt = 0; kt < nsteps; kt++) {
        if (kt + 1 < nsteps) {
            issue_stage(kt + 1, (kt + 1) & 1);
            CP_COMMIT();
            CP_WAIT1();
        } else {
            CP_WAIT0();
        }
        __syncthreads();

        uint32_t ab = smb + (uint32_t)(kt & 1) * GEMM_STAGE_ELEMS * 2;
        uint32_t al = ab + 128 * KST * 2;
        uint32_t bb = ab + 2 * 128 * KST * 2;
        uint32_t bl = ab + 3 * 128 * KST * 2;

#pragma unroll
        for (int kk = 0; kk < 2; kk++) {
            uint32_t fah[4][4], fal[4][4];
            {
                int row = wr * 64 + (lane & 15);
                int ko = kk * 16 + (lane >> 4) * 8;
#pragma unroll
                for (int mt = 0; mt < 4; mt++) {
                    uint32_t off = (uint32_t)(((row + mt * 16) * KST + ko) * 2);
                    ldsm_x4(fah[mt], ab + off);
                    ldsm_x4(fal[mt], al + off);
                }
            }
            uint32_t fbh[2][4], fbl[2][4];
            {
                int row = wc * 32 + (lane & 7) + ((lane >> 4) << 3);
                int ko = kk * 16 + ((lane >> 3) & 1) * 8;
#pragma unroll
                for (int p = 0; p < 2; p++) {
                    uint32_t off = (uint32_t)(((row + p * 16) * KST + ko) * 2);
                    ldsm_x4(fbh[p], bb + off);
                    ldsm_x4(fbl[p], bl + off);
                }
            }
#pragma unroll
            for (int mt = 0; mt < 4; mt++) {
#pragma unroll
                for (int p = 0; p < 2; p++) {
                    mma_bf16(acc[mt][2 * p],     fah[mt], fbh[p][0], fbh[p][1]);
                    mma_bf16(acc[mt][2 * p],     fah[mt], fbl[p][0], fbl[p][1]);
                    mma_bf16(acc[mt][2 * p],     fal[mt], fbh[p][0], fbh[p][1]);
                    mma_bf16(acc[mt][2 * p + 1], fah[mt], fbh[p][2], fbh[p][3]);
                    mma_bf16(acc[mt][2 * p + 1], fah[mt], fbl[p][2], fbl[p][3]);
                    mma_bf16(acc[mt][2 * p + 1], fal[mt], fbh[p][2], fbh[p][3]);
                }
            }
        }
        __syncthreads();
    }

    // epilogue
#pragma unroll
    for (int mt = 0; mt < 4; mt++) {
        int row = bm + wr * 64 + mt * 16 + g;
#pragma unroll
        for (int nt = 0; nt < 4; nt++) {
            int col = bn + wc * 32 + nt * 8 + 2 * tg;
            float bx = bias[col], by = bias[col + 1];
            float v00 = acc[mt][nt][0] + bx, v01 = acc[mt][nt][1] + by;
            float v10 = acc[mt][nt][2] + bx, v11 = acc[mt][nt][3] + by;
            if (SPLIT_OUT) {
                uint32_t h0, l0, h1, l1;
                split2(v00, v01, h0, l0);
                split2(v10, v11, h1, l1);
                *(uint32_t*)&Ch[(size_t)row * N + col]       = h0;
                *(uint32_t*)&Cl[(size_t)row * N + col]       = l0;
                *(uint32_t*)&Ch[(size_t)(row + 8) * N + col] = h1;
                *(uint32_t*)&Cl[(size_t)(row + 8) * N + col] = l1;
            } else {
                *(float2*)&Cf[(size_t)row * N + col]       = make_float2(v00, v01);
                *(float2*)&Cf[(size_t)(row + 8) * N + col] = make_float2(v10, v11);
            }
        }
    }
}

// ============================================================
// Flash attention, pre-split bf16 inputs, cp.async double buffer.
// CTA: 1 head x 128 q rows, 8 warps (16 q rows each), 64-key tiles.
// ============================================================
#define AST 72   // smem row stride (bf16 elems) = 144B
#define OQH 0
#define OQL (128 * AST)
#define OSTAGE (2 * 128 * AST)                 // start of K/V stages
#define STAGE_ELEMS (4 * 64 * AST)             // Kh,Kl,Vh,Vl
#define ATT_SMEM_BYTES ((OSTAGE + 2 * STAGE_ELEMS) * 2)

__global__ __launch_bounds__(256)
void flash_attn_split(const __nv_bfloat16* __restrict__ qkvh,
                      const __nv_bfloat16* __restrict__ qkvl,
                      __nv_bfloat16* __restrict__ ctxh,
                      __nv_bfloat16* __restrict__ ctxl)
{
    extern __shared__ __nv_bfloat16 sm[];

    const int h = blockIdx.y;
    const int qb = blockIdx.x;
    const int tid = threadIdx.x;
    const int w = tid >> 5, lane = tid & 31;
    const int g = lane >> 2, tg = lane & 3;

    const uint32_t smb = smaddr(sm);

    const size_t qoff = (size_t)qb * 128 * QKVDIM + h * DH;
    const size_t koff = DMODEL + (size_t)h * DH;
    const size_t voff = 2 * DMODEL + (size_t)h * DH;

    // ---- Q tile: 128 rows x 8 chunks x (h,l) ----
#pragma unroll
    for (int i = 0; i < 4; i++) {
        int idx = tid + i * 256;          // 1024
        int r = idx >> 3, c = idx & 7;
        uint32_t d = smb + (uint32_t)(r * AST + c * 8) * 2;
        CP16(d,                 qkvh + qoff + (size_t)r * QKVDIM + c * 8);
        CP16(d + OQL * 2,       qkvl + qoff + (size_t)r * QKVDIM + c * 8);
    }
    // ---- K/V stage 0 ----
    auto issue_kv = [&](int kt, int stage) {
        uint32_t base = smb + (uint32_t)(OSTAGE + stage * STAGE_ELEMS) * 2;
        size_t rofs = (size_t)kt * 64 * QKVDIM;
#pragma unroll
        for (int i = 0; i < 2; i++) {
            int idx = tid + i * 256;      // 512
            int r = idx >> 3, c = idx & 7;
            uint32_t d = base + (uint32_t)(r * AST + c * 8) * 2;
            size_t srow = rofs + (size_t)r * QKVDIM + c * 8;
            CP16(d,                     qkvh + koff + srow);
            CP16(d + 64 * AST * 2,      qkvl + koff + srow);
            CP16(d + 2 * 64 * AST * 2,  qkvh + voff + srow);
            CP16(d + 3 * 64 * AST * 2,  qkvl + voff + srow);
        }
    };
    issue_kv(0, 0);
    CP_COMMIT();

    uint32_t qh[4][4], ql[4][4];
    float m0 = -1e30f, m1 = -1e30f, l0 = 0.f, l1 = 0.f;
    float o[8][4];
#pragma unroll
    for (int t = 0; t < 8; t++)
#pragma unroll
        for (int c = 0; c < 4; c++) o[t][c] = 0.f;

    const int NT = SEQ / 64;
    for (int kt = 0; kt < NT; kt++) {
        if (kt + 1 < NT) {
            issue_kv(kt + 1, (kt + 1) & 1);
            CP_COMMIT();
            CP_WAIT1();
        } else {
            CP_WAIT0();
        }
        __syncthreads();

        if (kt == 0) {
            // Q fragments once (Q tile was in the first group)
            int row = w * 16 + (lane & 15);
#pragma unroll
            for (int kk = 0; kk < 4; kk++) {
                uint32_t off = (uint32_t)((row * AST + kk * 16 + (lane >> 4) * 8) * 2);
                ldsm_x4(qh[kk], smb + off);
                ldsm_x4(ql[kk], smb + OQL * 2 + off);
            }
        }

        uint32_t kb = smb + (uint32_t)(OSTAGE + (kt & 1) * STAGE_ELEMS) * 2;
        uint32_t klb = kb + 64 * AST * 2;
        uint32_t vb = kb + 2 * 64 * AST * 2;
        uint32_t vlb = kb + 3 * 64 * AST * 2;

        // ---- S = Q K^T ----
        float s[8][4];
#pragma unroll
        for (int t = 0; t < 8; t++)
#pragma unroll
            for (int c = 0; c < 4; c++) s[t][c] = 0.f;

#pragma unroll
        for (int kk = 0; kk < 4; kk++) {
            int nrow = (lane & 7) + ((lane >> 4) << 3);
            int ko = kk * 16 + ((lane >> 3) & 1) * 8;
            uint32_t kbh[4][4], kbl2[4][4];
#pragma unroll
            for (int p = 0; p < 4; p++) {
                uint32_t off = (uint32_t)(((nrow + p * 16) * AST + ko) * 2);
                ldsm_x4(kbh[p], kb + off);
                ldsm_x4(kbl2[p], klb + off);
            }
#pragma unroll
            for (int p = 0; p < 4; p++) {
                mma_bf16(s[2 * p],     qh[kk], kbh[p][0], kbh[p][1]);
                mma_bf16(s[2 * p],     qh[kk], kbl2[p][0], kbl2[p][1]);
                mma_bf16(s[2 * p],     ql[kk], kbh[p][0], kbh[p][1]);
                mma_bf16(s[2 * p + 1], qh[kk], kbh[p][2], kbh[p][3]);
                mma_bf16(s[2 * p + 1], qh[kk], kbl2[p][2], kbl2[p][3]);
                mma_bf16(s[2 * p + 1], ql[kk], kbh[p][2], kbh[p][3]);
            }
        }
        // scale logits (exact power of two)
#pragma unroll
        for (int t = 0; t < 8; t++)
#pragma unroll
            for (int c = 0; c < 4; c++) s[t][c] *= 0.125f;

        // ---- online softmax ----
        {
            float mx = s[0][0];
#pragma unroll
            for (int t = 0; t < 8; t++) mx = fmaxf(mx, fmaxf(s[t][0], s[t][1]));
            mx = fmaxf(mx, __shfl_xor_sync(0xffffffffu, mx, 1));
            mx = fmaxf(mx, __shfl_xor_sync(0xffffffffu, mx, 2));
            float mn = fmaxf(m0, mx);
            float corr = __expf(m0 - mn);
            float sum = 0.f;
#pragma unroll
            for (int t = 0; t < 8; t++) {
                s[t][0] = __expf(s[t][0] - mn);
                s[t][1] = __expf(s[t][1] - mn);
                sum += s[t][0] + s[t][1];
            }
            sum += __shfl_xor_sync(0xffffffffu, sum, 1);
            sum += __shfl_xor_sync(0xffffffffu, sum, 2);
            l0 = l0 * corr + sum; m0 = mn;
#pragma unroll
            for (int t = 0; t < 8; t++) { o[t][0] *= corr; o[t][1] *= corr; }
        }
        {
            float mx = s[0][2];
#pragma unroll
            for (int t = 0; t < 8; t++) mx = fmaxf(mx, fmaxf(s[t][2], s[t][3]));
            mx = fmaxf(mx, __shfl_xor_sync(0xffffffffu, mx, 1));
            mx = fmaxf(mx, __shfl_xor_sync(0xffffffffu, mx, 2));
            float mn = fmaxf(m1, mx);
            float corr = __expf(m1 - mn);
            float sum = 0.f;
#pragma unroll
            for (int t = 0; t < 8; t++) {
                s[t][2] = __expf(s[t][2] - mn);
                s[t][3] = __expf(s[t][3] - mn);
                sum += s[t][2] + s[t][3];
            }
            sum += __shfl_xor_sync(0xffffffffu, sum, 1);
            sum += __shfl_xor_sync(0xffffffffu, sum, 2);
            l1 = l1 * corr + sum; m1 = mn;
#pragma unroll
            for (int t = 0; t < 8; t++) { o[t][2] *= corr; o[t][3] *= corr; }
        }

        // ---- pack P fragments ----
        uint32_t pah[4][4], pal[4][4];
#pragma unroll
        for (int t2 = 0; t2 < 4; t2++) {
            split2(s[2 * t2][0],     s[2 * t2][1],     pah[t2][0], pal[t2][0]);
            split2(s[2 * t2][2],     s[2 * t2][3],     pah[t2][1], pal[t2][1]);
            split2(s[2 * t2 + 1][0], s[2 * t2 + 1][1], pah[t2][2], pal[t2][2]);
            split2(s[2 * t2 + 1][2], s[2 * t2 + 1][3], pah[t2][3], pal[t2][3]);
        }

        // ---- O += P V ----
#pragma unroll
        for (int kk2 = 0; kk2 < 4; kk2++) {
            int krow = kk2 * 16 + (lane & 15);
            int no = (lane >> 4) * 8;
            uint32_t vbh[4][4], vbl2[4][4];
#pragma unroll
            for (int p = 0; p < 4; p++) {
                uint32_t off = (uint32_t)((krow * AST + p * 16 + no) * 2);
                ldsm_x4_t(vbh[p], vb + off);
                ldsm_x4_t(vbl2[p], vlb + off);
            }
#pragma unroll
            for (int p = 0; p < 4; p++) {
                mma_bf16(o[2 * p],     pah[kk2], vbh[p][0], vbh[p][1]);
                mma_bf16(o[2 * p],     pah[kk2], vbl2[p][0], vbl2[p][1]);
                mma_bf16(o[2 * p],     pal[kk2], vbh[p][0], vbh[p][1]);
                mma_bf16(o[2 * p + 1], pah[kk2], vbh[p][2], vbh[p][3]);
                mma_bf16(o[2 * p + 1], pah[kk2], vbl2[p][2], vbl2[p][3]);
                mma_bf16(o[2 * p + 1], pal[kk2], vbh[p][2], vbh[p][3]);
            }
        }
        __syncthreads();
    }

    // ---- epilogue: write ctx split bf16 ----
    float inv0 = 1.0f / l0, inv1 = 1.0f / l1;
    int row0 = qb * 128 + w * 16 + g;
#pragma unroll
    for (int t = 0; t < 8; t++) {
        int d = h * DH + 8 * t + 2 * tg;
        uint32_t h0, l0u, h1, l1u;
        split2(o[t][0] * inv0, o[t][1] * inv0, h0, l0u);
        split2(o[t][2] * inv1, o[t][3] * inv1, h1, l1u);
        *(uint32_t*)&ctxh[(size_t)row0 * DMODEL + d]       = h0;
        *(uint32_t*)&ctxl[(size_t)row0 * DMODEL + d]       = l0u;
        *(uint32_t*)&ctxh[(size_t)(row0 + 8) * DMODEL + d] = h1;
        *(uint32_t*)&ctxl[(size_t)(row0 + 8) * DMODEL + d] = l1u;
    }
}

// ============================================================
extern "C" void kernel_launch(void* const* d_in, const int* in_sizes, int n_in,
                              void* d_out, int out_size)
{
    const float* x     = (const float*)d_in[0];
    const float* w_qkv = (const float*)d_in[1];
    const float* b_qkv = (const float*)d_in[2];
    const float* w_out = (const float*)d_in[3];
    const float* b_out = (const float*)d_in[4];
    float* out = (float*)d_out;

    __nv_bfloat16 *xh, *xl, *wqh, *wql, *woh, *wol, *qkvh, *qkvl, *ctxh, *ctxl;
    cudaGetSymbolAddress((void**)&xh, g_xh);   cudaGetSymbolAddress((void**)&xl, g_xl);
    cudaGetSymbolAddress((void**)&wqh, g_wqh); cudaGetSymbolAddress((void**)&wql, g_wql);
    cudaGetSymbolAddress((void**)&woh, g_woh); cudaGetSymbolAddress((void**)&wol, g_wol);
    cudaGetSymbolAddress((void**)&qkvh, g_qkvh); cudaGetSymbolAddress((void**)&qkvl, g_qkvl);
    cudaGetSymbolAddress((void**)&ctxh, g_ctxh); cudaGetSymbolAddress((void**)&ctxl, g_ctxl);

    // 0) prepass splits
    {
        int n4;
        n4 = SEQ * DMODEL / 4;
        split_kernel<<<(n4 + 255) / 256, 256>>>(x, xh, xl, n4);
        n4 = QKVDIM * DMODEL / 4;
        split_kernel<<<(n4 + 255) / 256, 256>>>(w_qkv, wqh, wql, n4);
        n4 = DMODEL * DMODEL / 4;
        split_kernel<<<(n4 + 255) / 256, 256>>>(w_out, woh, wol, n4);
    }

    // 1) QKV projection -> split bf16 qkv
    {
        cudaFuncSetAttribute(gemm_split<true>,
                             cudaFuncAttributeMaxDynamicSharedMemorySize, GEMM_SMEM_BYTES);
        dim3 grid(QKVDIM / 128, SEQ / 128);
        gemm_split<true><<<grid, 256, GEMM_SMEM_BYTES>>>(
            xh, xl, wqh, wql, b_qkv, nullptr, qkvh, qkvl, SEQ, QKVDIM, DMODEL);
    }

    // 2) flash attention -> split bf16 ctx
    {
        cudaFuncSetAttribute(flash_attn_split,
                             cudaFuncAttributeMaxDynamicSharedMemorySize, ATT_SMEM_BYTES);
        dim3 grid(SEQ / 128, NHEADS);
        flash_attn_split<<<grid, 256, ATT_SMEM_BYTES>>>(qkvh, qkvl, ctxh, ctxl);
    }

    // 3) output projection -> fp32 out
    {
        cudaFuncSetAttribute(gemm_split<false>,
                             cudaFuncAttributeMaxDynamicSharedMemorySize, GEMM_SMEM_BYTES);
        dim3 grid(DMODEL / 128, SEQ / 128);
        gemm_split<false><<<grid, 256, GEMM_SMEM_BYTES>>>(
            ctxh, ctxl, woh, wol, b_out, out, nullptr, nullptr, SEQ, DMODEL, DMODEL);
    }
}

// round 5
// speedup vs baseline: 1.1180x; 1.1180x over previous
#include <cuda_runtime.h>
#include <cuda_bf16.h>
#include <cstdint>

#define SEQ     4096
#define DMODEL  1024
#define NHEADS  16
#define DH      64
#define QKVDIM  (3 * DMODEL)

// ---------------- scratch (split bf16 hi/lo) ----------------
__device__ __nv_bfloat16 g_xh[(size_t)SEQ * DMODEL],    g_xl[(size_t)SEQ * DMODEL];
__device__ __nv_bfloat16 g_wqh[(size_t)QKVDIM * DMODEL], g_wql[(size_t)QKVDIM * DMODEL];
__device__ __nv_bfloat16 g_woh[(size_t)DMODEL * DMODEL], g_wol[(size_t)DMODEL * DMODEL];
__device__ __nv_bfloat16 g_qkvh[(size_t)SEQ * QKVDIM],  g_qkvl[(size_t)SEQ * QKVDIM];
__device__ __nv_bfloat16 g_ctxh[(size_t)SEQ * DMODEL],  g_ctxl[(size_t)SEQ * DMODEL];

// ============================================================
// helpers
// ============================================================
__device__ __forceinline__ uint32_t smaddr(const void* p) {
    return static_cast<uint32_t>(__cvta_generic_to_shared(p));
}
__device__ __forceinline__ uint32_t b2u(__nv_bfloat162 v) {
    return *reinterpret_cast<uint32_t*>(&v);
}
__device__ __forceinline__ void split2(float x, float y, uint32_t& hi, uint32_t& lo) {
    __nv_bfloat162 h = __float22bfloat162_rn(make_float2(x, y));
    float2 hf = __bfloat1622float2(h);
    __nv_bfloat162 l = __float22bfloat162_rn(make_float2(x - hf.x, y - hf.y));
    hi = b2u(h); lo = b2u(l);
}
__device__ __forceinline__ void ldsm_x4(uint32_t* r, uint32_t addr) {
    asm volatile("ldmatrix.sync.aligned.m8n8.x4.shared.b16 {%0,%1,%2,%3}, [%4];"
                 : "=r"(r[0]), "=r"(r[1]), "=r"(r[2]), "=r"(r[3]) : "r"(addr));
}
__device__ __forceinline__ void ldsm_x4_t(uint32_t* r, uint32_t addr) {
    asm volatile("ldmatrix.sync.aligned.m8n8.x4.trans.shared.b16 {%0,%1,%2,%3}, [%4];"
                 : "=r"(r[0]), "=r"(r[1]), "=r"(r[2]), "=r"(r[3]) : "r"(addr));
}
__device__ __forceinline__ void mma_bf16(float* d, const uint32_t* a, uint32_t b0, uint32_t b1) {
    asm volatile(
        "mma.sync.aligned.m16n8k16.row.col.f32.bf16.bf16.f32 "
        "{%0,%1,%2,%3}, {%4,%5,%6,%7}, {%8,%9}, {%0,%1,%2,%3};"
        : "+f"(d[0]), "+f"(d[1]), "+f"(d[2]), "+f"(d[3])
        : "r"(a[0]), "r"(a[1]), "r"(a[2]), "r"(a[3]), "r"(b0), "r"(b1));
}
#define CP16(dst, src) asm volatile("cp.async.cg.shared.global [%0], [%1], 16;" :: "r"(dst), "l"(src))
#define CP_COMMIT()    asm volatile("cp.async.commit_group;")
#define CP_WAIT1()     asm volatile("cp.async.wait_group 1;")
#define CP_WAIT0()     asm volatile("cp.async.wait_group 0;")

// ============================================================
// prepass: split fp32 -> bf16 hi/lo
// ============================================================
__global__ void split_kernel(const float* __restrict__ in,
                             __nv_bfloat16* __restrict__ h,
                             __nv_bfloat16* __restrict__ l, int n4)
{
    int i = blockIdx.x * blockDim.x + threadIdx.x;
    if (i >= n4) return;
    float4 v = ((const float4*)in)[i];
    uint32_t h0, h1, l0, l1;
    split2(v.x, v.y, h0, l0);
    split2(v.z, v.w, h1, l1);
    ((uint2*)h)[i] = make_uint2(h0, h1);
    ((uint2*)l)[i] = make_uint2(l0, l1);
}

// ============================================================
// GEMM (mma.sync): C[M,N] = (Ah+Al)[M,K]*(Bh+Bl)[N,K]^T + bias
// CTA 128x128, 256 thr (8 warps 2x4), warp 64x32, k-step 32,
// cp.async double buffer.
// ============================================================
#define KST 40
#define GEMM_STAGE_ELEMS (4 * 128 * KST)
#define GEMM_SMEM_BYTES  (2 * GEMM_STAGE_ELEMS * 2)

template <bool SPLIT_OUT>
__global__ __launch_bounds__(256)
void gemm_split(const __nv_bfloat16* __restrict__ Ah, const __nv_bfloat16* __restrict__ Al,
                const __nv_bfloat16* __restrict__ Bh, const __nv_bfloat16* __restrict__ Bl,
                const float* __restrict__ bias,
                float* __restrict__ Cf,
                __nv_bfloat16* __restrict__ Ch, __nv_bfloat16* __restrict__ Cl,
                int M, int N, int K)
{
    extern __shared__ __nv_bfloat16 sm[];

    const int tid = threadIdx.x;
    const int w = tid >> 5, lane = tid & 31;
    const int wr = w >> 2, wc = w & 3;
    const int g = lane >> 2, tg = lane & 3;
    const int bm = blockIdx.y * 128, bn = blockIdx.x * 128;

    const uint32_t smb = smaddr(sm);

    float acc[4][4][4];
#pragma unroll
    for (int a = 0; a < 4; a++)
#pragma unroll
        for (int b = 0; b < 4; b++)
#pragma unroll
            for (int c = 0; c < 4; c++) acc[a][b][c] = 0.f;

    auto issue_stage = [&](int kt, int stage) {
        const size_t ko = (size_t)kt * 32;
        uint32_t base = smb + (uint32_t)stage * GEMM_STAGE_ELEMS * 2;
#pragma unroll
        for (int i = 0; i < 2; i++) {
            int idx = tid + i * 256;
            int r = idx >> 2, c = idx & 3;
            uint32_t d = base + (uint32_t)(r * KST + c * 8) * 2;
            CP16(d,                     Ah + (size_t)(bm + r) * K + ko + c * 8);
            CP16(d + 128 * KST * 2,     Al + (size_t)(bm + r) * K + ko + c * 8);
            CP16(d + 2 * 128 * KST * 2, Bh + (size_t)(bn + r) * K + ko + c * 8);
            CP16(d + 3 * 128 * KST * 2, Bl + (size_t)(bn + r) * K + ko + c * 8);
        }
    };

    const int nsteps = K >> 5;
    issue_stage(0, 0);
    CP_COMMIT();

    for (int kt = 0; kt < nsteps; kt++) {
        if (kt + 1 < nsteps) {
            issue_stage(kt + 1, (kt + 1) & 1);
            CP_COMMIT();
            CP_WAIT1();
        } else {
            CP_WAIT0();
        }
        __syncthreads();

        uint32_t ab = smb + (uint32_t)(kt & 1) * GEMM_STAGE_ELEMS * 2;
        uint32_t al = ab + 128 * KST * 2;
        uint32_t bb = ab + 2 * 128 * KST * 2;
        uint32_t bl = ab + 3 * 128 * KST * 2;

#pragma unroll
        for (int kk = 0; kk < 2; kk++) {
            uint32_t fah[4][4], fal[4][4];
            {
                int row = wr * 64 + (lane & 15);
                int ko = kk * 16 + (lane >> 4) * 8;
#pragma unroll
                for (int mt = 0; mt < 4; mt++) {
                    uint32_t off = (uint32_t)(((row + mt * 16) * KST + ko) * 2);
                    ldsm_x4(fah[mt], ab + off);
                    ldsm_x4(fal[mt], al + off);
                }
            }
            uint32_t fbh[2][4], fbl[2][4];
            {
                int row = wc * 32 + (lane & 7) + ((lane >> 4) << 3);
                int ko = kk * 16 + ((lane >> 3) & 1) * 8;
#pragma unroll
                for (int p = 0; p < 2; p++) {
                    uint32_t off = (uint32_t)(((row + p * 16) * KST + ko) * 2);
                    ldsm_x4(fbh[p], bb + off);
                    ldsm_x4(fbl[p], bl + off);
                }
            }
#pragma unroll
            for (int mt = 0; mt < 4; mt++) {
#pragma unroll
                for (int p = 0; p < 2; p++) {
                    mma_bf16(acc[mt][2 * p],     fah[mt], fbh[p][0], fbh[p][1]);
                    mma_bf16(acc[mt][2 * p],     fah[mt], fbl[p][0], fbl[p][1]);
                    mma_bf16(acc[mt][2 * p],     fal[mt], fbh[p][0], fbh[p][1]);
                    mma_bf16(acc[mt][2 * p + 1], fah[mt], fbh[p][2], fbh[p][3]);
                    mma_bf16(acc[mt][2 * p + 1], fah[mt], fbl[p][2], fbl[p][3]);
                    mma_bf16(acc[mt][2 * p + 1], fal[mt], fbh[p][2], fbh[p][3]);
                }
            }
        }
        __syncthreads();
    }

#pragma unroll
    for (int mt = 0; mt < 4; mt++) {
        int row = bm + wr * 64 + mt * 16 + g;
#pragma unroll
        for (int nt = 0; nt < 4; nt++) {
            int col = bn + wc * 32 + nt * 8 + 2 * tg;
            float bx = bias[col], by = bias[col + 1];
            float v00 = acc[mt][nt][0] + bx, v01 = acc[mt][nt][1] + by;
            float v10 = acc[mt][nt][2] + bx, v11 = acc[mt][nt][3] + by;
            if (SPLIT_OUT) {
                uint32_t h0, l0, h1, l1;
                split2(v00, v01, h0, l0);
                split2(v10, v11, h1, l1);
                *(uint32_t*)&Ch[(size_t)row * N + col]       = h0;
                *(uint32_t*)&Cl[(size_t)row * N + col]       = l0;
                *(uint32_t*)&Ch[(size_t)(row + 8) * N + col] = h1;
                *(uint32_t*)&Cl[(size_t)(row + 8) * N + col] = l1;
            } else {
                *(float2*)&Cf[(size_t)row * N + col]       = make_float2(v00, v01);
                *(float2*)&Cf[(size_t)(row + 8) * N + col] = make_float2(v10, v11);
            }
        }
    }
}

// ============================================================
// Flash attention v2: BM=64 rows/CTA, 128 threads (4 warps),
// Q fragments via direct LDG (no Q smem), K/V hi/lo double-buffered
// cp.async. smem 72KB -> 3 CTAs/SM.
// ============================================================
#define AST 72
#define STAGE_ELEMS (4 * 64 * AST)              // Kh,Kl,Vh,Vl
#define ATT_SMEM_BYTES (2 * STAGE_ELEMS * 2)    // 73728

__global__ __launch_bounds__(128, 3)
void flash_attn_v2(const __nv_bfloat16* __restrict__ qkvh,
                   const __nv_bfloat16* __restrict__ qkvl,
                   __nv_bfloat16* __restrict__ ctxh,
                   __nv_bfloat16* __restrict__ ctxl)
{
    extern __shared__ __nv_bfloat16 sm[];

    const int h = blockIdx.y;
    const int qb = blockIdx.x;
    const int tid = threadIdx.x;
    const int w = tid >> 5, lane = tid & 31;
    const int g = lane >> 2, tg = lane & 3;

    const uint32_t smb = smaddr(sm);

    const size_t koff = DMODEL + (size_t)h * DH;
    const size_t voff = 2 * DMODEL + (size_t)h * DH;

    // ---- Q fragments via direct LDG (m16n8k16 A layout) ----
    const int row0 = qb * 64 + w * 16;
    uint32_t qh[4][4], ql[4][4];
#pragma unroll
    for (int kk = 0; kk < 4; kk++) {
        size_t c = (size_t)h * DH + kk * 16 + 2 * tg;
        size_t rA = (size_t)(row0 + g) * QKVDIM + c;
        size_t rB = (size_t)(row0 + g + 8) * QKVDIM + c;
        qh[kk][0] = *(const uint32_t*)&qkvh[rA];
        qh[kk][1] = *(const uint32_t*)&qkvh[rB];
        qh[kk][2] = *(const uint32_t*)&qkvh[rA + 8];
        qh[kk][3] = *(const uint32_t*)&qkvh[rB + 8];
        ql[kk][0] = *(const uint32_t*)&qkvl[rA];
        ql[kk][1] = *(const uint32_t*)&qkvl[rB];
        ql[kk][2] = *(const uint32_t*)&qkvl[rA + 8];
        ql[kk][3] = *(const uint32_t*)&qkvl[rB + 8];
    }

    // ---- K/V stage fill ----
    auto issue_kv = [&](int kt, int stage) {
        uint32_t base = smb + (uint32_t)(stage * STAGE_ELEMS) * 2;
        size_t rofs = (size_t)kt * 64 * QKVDIM;
#pragma unroll
        for (int i = 0; i < 4; i++) {
            int idx = tid + i * 128;      // 512 chunks: 64 rows x 8
            int r = idx >> 3, c = idx & 7;
            uint32_t d = base + (uint32_t)(r * AST + c * 8) * 2;
            size_t srow = rofs + (size_t)r * QKVDIM + c * 8;
            CP16(d,                    qkvh + koff + srow);
            CP16(d + 64 * AST * 2,     qkvl + koff + srow);
            CP16(d + 2 * 64 * AST * 2, qkvh + voff + srow);
            CP16(d + 3 * 64 * AST * 2, qkvl + voff + srow);
        }
    };
    issue_kv(0, 0);
    CP_COMMIT();

    float m0 = -1e30f, m1 = -1e30f, l0 = 0.f, l1 = 0.f;
    float o[8][4];
#pragma unroll
    for (int t = 0; t < 8; t++)
#pragma unroll
        for (int c = 0; c < 4; c++) o[t][c] = 0.f;

    const int NT = SEQ / 64;
    for (int kt = 0; kt < NT; kt++) {
        if (kt + 1 < NT) {
            issue_kv(kt + 1, (kt + 1) & 1);
            CP_COMMIT();
            CP_WAIT1();
        } else {
            CP_WAIT0();
        }
        __syncthreads();

        uint32_t kb  = smb + (uint32_t)((kt & 1) * STAGE_ELEMS) * 2;
        uint32_t klb = kb + 64 * AST * 2;
        uint32_t vb  = kb + 2 * 64 * AST * 2;
        uint32_t vlb = kb + 3 * 64 * AST * 2;

        // ---- S = Q K^T ----
        float s[8][4];
#pragma unroll
        for (int t = 0; t < 8; t++)
#pragma unroll
            for (int c = 0; c < 4; c++) s[t][c] = 0.f;

#pragma unroll
        for (int kk = 0; kk < 4; kk++) {
            int nrow = (lane & 7) + ((lane >> 4) << 3);
            int ko = kk * 16 + ((lane >> 3) & 1) * 8;
            uint32_t kbh[4][4], kbl2[4][4];
#pragma unroll
            for (int p = 0; p < 4; p++) {
                uint32_t off = (uint32_t)(((nrow + p * 16) * AST + ko) * 2);
                ldsm_x4(kbh[p], kb + off);
                ldsm_x4(kbl2[p], klb + off);
            }
#pragma unroll
            for (int p = 0; p < 4; p++) {
                mma_bf16(s[2 * p],     qh[kk], kbh[p][0], kbh[p][1]);
                mma_bf16(s[2 * p],     qh[kk], kbl2[p][0], kbl2[p][1]);
                mma_bf16(s[2 * p],     ql[kk], kbh[p][0], kbh[p][1]);
                mma_bf16(s[2 * p + 1], qh[kk], kbh[p][2], kbh[p][3]);
                mma_bf16(s[2 * p + 1], qh[kk], kbl2[p][2], kbl2[p][3]);
                mma_bf16(s[2 * p + 1], ql[kk], kbh[p][2], kbh[p][3]);
            }
        }
#pragma unroll
        for (int t = 0; t < 8; t++)
#pragma unroll
            for (int c = 0; c < 4; c++) s[t][c] *= 0.125f;

        // ---- online softmax ----
        {
            float mx = s[0][0];
#pragma unroll
            for (int t = 0; t < 8; t++) mx = fmaxf(mx, fmaxf(s[t][0], s[t][1]));
            mx = fmaxf(mx, __shfl_xor_sync(0xffffffffu, mx, 1));
            mx = fmaxf(mx, __shfl_xor_sync(0xffffffffu, mx, 2));
            float mn = fmaxf(m0, mx);
            float corr = __expf(m0 - mn);
            float sum = 0.f;
#pragma unroll
            for (int t = 0; t < 8; t++) {
                s[t][0] = __expf(s[t][0] - mn);
                s[t][1] = __expf(s[t][1] - mn);
                sum += s[t][0] + s[t][1];
            }
            sum += __shfl_xor_sync(0xffffffffu, sum, 1);
            sum += __shfl_xor_sync(0xffffffffu, sum, 2);
            l0 = l0 * corr + sum; m0 = mn;
#pragma unroll
            for (int t = 0; t < 8; t++) { o[t][0] *= corr; o[t][1] *= corr; }
        }
        {
            float mx = s[0][2];
#pragma unroll
            for (int t = 0; t < 8; t++) mx = fmaxf(mx, fmaxf(s[t][2], s[t][3]));
            mx = fmaxf(mx, __shfl_xor_sync(0xffffffffu, mx, 1));
            mx = fmaxf(mx, __shfl_xor_sync(0xffffffffu, mx, 2));
            float mn = fmaxf(m1, mx);
            float corr = __expf(m1 - mn);
            float sum = 0.f;
#pragma unroll
            for (int t = 0; t < 8; t++) {
                s[t][2] = __expf(s[t][2] - mn);
                s[t][3] = __expf(s[t][3] - mn);
                sum += s[t][2] + s[t][3];
            }
            sum += __shfl_xor_sync(0xffffffffu, sum, 1);
            sum += __shfl_xor_sync(0xffffffffu, sum, 2);
            l1 = l1 * corr + sum; m1 = mn;
#pragma unroll
            for (int t = 0; t < 8; t++) { o[t][2] *= corr; o[t][3] *= corr; }
        }

        // ---- pack P fragments ----
        uint32_t pah[4][4], pal[4][4];
#pragma unroll
        for (int t2 = 0; t2 < 4; t2++) {
            split2(s[2 * t2][0],     s[2 * t2][1],     pah[t2][0], pal[t2][0]);
            split2(s[2 * t2][2],     s[2 * t2][3],     pah[t2][1], pal[t2][1]);
            split2(s[2 * t2 + 1][0], s[2 * t2 + 1][1], pah[t2][2], pal[t2][2]);
            split2(s[2 * t2 + 1][2], s[2 * t2 + 1][3], pah[t2][3], pal[t2][3]);
        }

        // ---- O += P V ----
#pragma unroll
        for (int kk2 = 0; kk2 < 4; kk2++) {
            int krow = kk2 * 16 + (lane & 15);
            int no = (lane >> 4) * 8;
            uint32_t vbh[4][4], vbl2[4][4];
#pragma unroll
            for (int p = 0; p < 4; p++) {
                uint32_t off = (uint32_t)((krow * AST + p * 16 + no) * 2);
                ldsm_x4_t(vbh[p], vb + off);
                ldsm_x4_t(vbl2[p], vlb + off);
            }
#pragma unroll
            for (int p = 0; p < 4; p++) {
                mma_bf16(o[2 * p],     pah[kk2], vbh[p][0], vbh[p][1]);
                mma_bf16(o[2 * p],     pah[kk2], vbl2[p][0], vbl2[p][1]);
                mma_bf16(o[2 * p],     pal[kk2], vbh[p][0], vbh[p][1]);
                mma_bf16(o[2 * p + 1], pah[kk2], vbh[p][2], vbh[p][3]);
                mma_bf16(o[2 * p + 1], pah[kk2], vbl2[p][2], vbl2[p][3]);
                mma_bf16(o[2 * p + 1], pal[kk2], vbh[p][2], vbh[p][3]);
            }
        }
        __syncthreads();
    }

    // ---- epilogue: write ctx split bf16 ----
    float inv0 = 1.0f / l0, inv1 = 1.0f / l1;
#pragma unroll
    for (int t = 0; t < 8; t++) {
        int d = h * DH + 8 * t + 2 * tg;
        uint32_t h0, l0u, h1, l1u;
        split2(o[t][0] * inv0, o[t][1] * inv0, h0, l0u);
        split2(o[t][2] * inv1, o[t][3] * inv1, h1, l1u);
        *(uint32_t*)&ctxh[(size_t)(row0 + g) * DMODEL + d]     = h0;
        *(uint32_t*)&ctxl[(size_t)(row0 + g) * DMODEL + d]     = l0u;
        *(uint32_t*)&ctxh[(size_t)(row0 + g + 8) * DMODEL + d] = h1;
        *(uint32_t*)&ctxl[(size_t)(row0 + g + 8) * DMODEL + d] = l1u;
    }
}

// ============================================================
extern "C" void kernel_launch(void* const* d_in, const int* in_sizes, int n_in,
                              void* d_out, int out_size)
{
    const float* x     = (const float*)d_in[0];
    const float* w_qkv = (const float*)d_in[1];
    const float* b_qkv = (const float*)d_in[2];
    const float* w_out = (const float*)d_in[3];
    const float* b_out = (const float*)d_in[4];
    float* out = (float*)d_out;

    __nv_bfloat16 *xh, *xl, *wqh, *wql, *woh, *wol, *qkvh, *qkvl, *ctxh, *ctxl;
    cudaGetSymbolAddress((void**)&xh, g_xh);   cudaGetSymbolAddress((void**)&xl, g_xl);
    cudaGetSymbolAddress((void**)&wqh, g_wqh); cudaGetSymbolAddress((void**)&wql, g_wql);
    cudaGetSymbolAddress((void**)&woh, g_woh); cudaGetSymbolAddress((void**)&wol, g_wol);
    cudaGetSymbolAddress((void**)&qkvh, g_qkvh); cudaGetSymbolAddress((void**)&qkvl, g_qkvl);
    cudaGetSymbolAddress((void**)&ctxh, g_ctxh); cudaGetSymbolAddress((void**)&ctxl, g_ctxl);

    // 0) prepass splits
    {
        int n4;
        n4 = SEQ * DMODEL / 4;
        split_kernel<<<(n4 + 255) / 256, 256>>>(x, xh, xl, n4);
        n4 = QKVDIM * DMODEL / 4;
        split_kernel<<<(n4 + 255) / 256, 256>>>(w_qkv, wqh, wql, n4);
        n4 = DMODEL * DMODEL / 4;
        split_kernel<<<(n4 + 255) / 256, 256>>>(w_out, woh, wol, n4);
    }

    // 1) QKV projection -> split bf16 qkv
    {
        cudaFuncSetAttribute(gemm_split<true>,
                             cudaFuncAttributeMaxDynamicSharedMemorySize, GEMM_SMEM_BYTES);
        dim3 grid(QKVDIM / 128, SEQ / 128);
        gemm_split<true><<<grid, 256, GEMM_SMEM_BYTES>>>(
            xh, xl, wqh, wql, b_qkv, nullptr, qkvh, qkvl, SEQ, QKVDIM, DMODEL);
    }

    // 2) flash attention -> split bf16 ctx
    {
        cudaFuncSetAttribute(flash_attn_v2,
                             cudaFuncAttributeMaxDynamicSharedMemorySize, ATT_SMEM_BYTES);
        dim3 grid(SEQ / 64, NHEADS);
        flash_attn_v2<<<grid, 128, ATT_SMEM_BYTES>>>(qkvh, qkvl, ctxh, ctxl);
    }

    // 3) output projection -> fp32 out
    {
        cudaFuncSetAttribute(gemm_split<false>,
                             cudaFuncAttributeMaxDynamicSharedMemorySize, GEMM_SMEM_BYTES);
        dim3 grid(DMODEL / 128, SEQ / 128);
        gemm_split<false><<<grid, 256, GEMM_SMEM_BYTES>>>(
            ctxh, ctxl, woh, wol, b_out, out, nullptr, nullptr, SEQ, DMODEL, DMODEL);
    }
}

// round 6
// speedup vs baseline: 1.4011x; 1.2532x over previous
#include <cuda_runtime.h>
#include <cuda_bf16.h>
#include <cuda_fp16.h>
#include <cstdint>

#define SEQ     4096
#define DMODEL  1024
#define NHEADS  16
#define DH      64
#define QKVDIM  (3 * DMODEL)

// ---------------- scratch ----------------
__device__ __half        g_xf[(size_t)SEQ * DMODEL];
__device__ __half        g_wqf[(size_t)QKVDIM * DMODEL];
__device__ __half        g_wof[(size_t)DMODEL * DMODEL];
__device__ __nv_bfloat16 g_qkvh[(size_t)SEQ * QKVDIM], g_qkvl[(size_t)SEQ * QKVDIM];
__device__ __half        g_ctxf[(size_t)SEQ * DMODEL];

// ============================================================
// helpers
// ============================================================
__device__ __forceinline__ uint32_t smaddr(const void* p) {
    return static_cast<uint32_t>(__cvta_generic_to_shared(p));
}
__device__ __forceinline__ uint32_t b2u(__nv_bfloat162 v) {
    return *reinterpret_cast<uint32_t*>(&v);
}
__device__ __forceinline__ void split2(float x, float y, uint32_t& hi, uint32_t& lo) {
    __nv_bfloat162 h = __float22bfloat162_rn(make_float2(x, y));
    float2 hf = __bfloat1622float2(h);
    __nv_bfloat162 l = __float22bfloat162_rn(make_float2(x - hf.x, y - hf.y));
    hi = b2u(h); lo = b2u(l);
}
__device__ __forceinline__ void ldsm_x4(uint32_t* r, uint32_t addr) {
    asm volatile("ldmatrix.sync.aligned.m8n8.x4.shared.b16 {%0,%1,%2,%3}, [%4];"
                 : "=r"(r[0]), "=r"(r[1]), "=r"(r[2]), "=r"(r[3]) : "r"(addr));
}
__device__ __forceinline__ void ldsm_x4_t(uint32_t* r, uint32_t addr) {
    asm volatile("ldmatrix.sync.aligned.m8n8.x4.trans.shared.b16 {%0,%1,%2,%3}, [%4];"
                 : "=r"(r[0]), "=r"(r[1]), "=r"(r[2]), "=r"(r[3]) : "r"(addr));
}
__device__ __forceinline__ void mma_bf16(float* d, const uint32_t* a, uint32_t b0, uint32_t b1) {
    asm volatile(
        "mma.sync.aligned.m16n8k16.row.col.f32.bf16.bf16.f32 "
        "{%0,%1,%2,%3}, {%4,%5,%6,%7}, {%8,%9}, {%0,%1,%2,%3};"
        : "+f"(d[0]), "+f"(d[1]), "+f"(d[2]), "+f"(d[3])
        : "r"(a[0]), "r"(a[1]), "r"(a[2]), "r"(a[3]), "r"(b0), "r"(b1));
}
__device__ __forceinline__ void mma_fp16(float* d, const uint32_t* a, uint32_t b0, uint32_t b1) {
    asm volatile(
        "mma.sync.aligned.m16n8k16.row.col.f32.f16.f16.f32 "
        "{%0,%1,%2,%3}, {%4,%5,%6,%7}, {%8,%9}, {%0,%1,%2,%3};"
        : "+f"(d[0]), "+f"(d[1]), "+f"(d[2]), "+f"(d[3])
        : "r"(a[0]), "r"(a[1]), "r"(a[2]), "r"(a[3]), "r"(b0), "r"(b1));
}
#define CP16(dst, src) asm volatile("cp.async.cg.shared.global [%0], [%1], 16;" :: "r"(dst), "l"(src))
#define CP_COMMIT()    asm volatile("cp.async.commit_group;")
#define CP_WAIT1()     asm volatile("cp.async.wait_group 1;")
#define CP_WAIT0()     asm volatile("cp.async.wait_group 0;")

// ============================================================
// prepass: fp32 -> fp16
// ============================================================
__global__ void tohalf_kernel(const float* __restrict__ in,
                              __half* __restrict__ o, int n4)
{
    int i = blockIdx.x * blockDim.x + threadIdx.x;
    if (i >= n4) return;
    float4 v = ((const float4*)in)[i];
    __half2 a = __float22half2_rn(make_float2(v.x, v.y));
    __half2 b = __float22half2_rn(make_float2(v.z, v.w));
    ((uint2*)o)[i] = make_uint2(*(uint32_t*)&a, *(uint32_t*)&b);
}

// ============================================================
// fp16 single-pass GEMM: C[M,N] = A[M,K]*B[N,K]^T + bias
// CTA 128x128, 256 thr (8 warps 2x4), warp 64x32, k-step 32,
// cp.async double buffer. SPLIT_OUT: write split bf16 hi/lo.
// ============================================================
#define KST 40
#define HSTAGE (2 * 128 * KST)                 // A,B fp16 per stage
#define HGEMM_SMEM_BYTES (2 * HSTAGE * 2)      // 40960

template <bool SPLIT_OUT>
__global__ __launch_bounds__(256)
void gemm_fp16(const __half* __restrict__ A, const __half* __restrict__ B,
               const float* __restrict__ bias,
               float* __restrict__ Cf,
               __nv_bfloat16* __restrict__ Ch, __nv_bfloat16* __restrict__ Cl,
               int M, int N, int K)
{
    extern __shared__ __half hsm[];

    const int tid = threadIdx.x;
    const int w = tid >> 5, lane = tid & 31;
    const int wr = w >> 2, wc = w & 3;
    const int g = lane >> 2, tg = lane & 3;
    const int bm = blockIdx.y * 128, bn = blockIdx.x * 128;

    const uint32_t smb = smaddr(hsm);

    float acc[4][4][4];
#pragma unroll
    for (int a = 0; a < 4; a++)
#pragma unroll
        for (int b = 0; b < 4; b++)
#pragma unroll
            for (int c = 0; c < 4; c++) acc[a][b][c] = 0.f;

    auto issue_stage = [&](int kt, int stage) {
        const size_t ko = (size_t)kt * 32;
        uint32_t base = smb + (uint32_t)stage * HSTAGE * 2;
#pragma unroll
        for (int i = 0; i < 2; i++) {
            int idx = tid + i * 256;
            int r = idx >> 2, c = idx & 3;
            uint32_t d = base + (uint32_t)(r * KST + c * 8) * 2;
            CP16(d,                 A + (size_t)(bm + r) * K + ko + c * 8);
            CP16(d + 128 * KST * 2, B + (size_t)(bn + r) * K + ko + c * 8);
        }
    };

    const int nsteps = K >> 5;
    issue_stage(0, 0);
    CP_COMMIT();

    for (int kt = 0; kt < nsteps; kt++) {
        if (kt + 1 < nsteps) {
            issue_stage(kt + 1, (kt + 1) & 1);
            CP_COMMIT();
            CP_WAIT1();
        } else {
            CP_WAIT0();
        }
        __syncthreads();

        uint32_t ab = smb + (uint32_t)(kt & 1) * HSTAGE * 2;
        uint32_t bb = ab + 128 * KST * 2;

#pragma unroll
        for (int kk = 0; kk < 2; kk++) {
            uint32_t fa[4][4];
            {
                int row = wr * 64 + (lane & 15);
                int ko = kk * 16 + (lane >> 4) * 8;
#pragma unroll
                for (int mt = 0; mt < 4; mt++)
                    ldsm_x4(fa[mt], ab + (uint32_t)(((row + mt * 16) * KST + ko) * 2));
            }
            uint32_t fb[2][4];
            {
                int row = wc * 32 + (lane & 7) + ((lane >> 4) << 3);
                int ko = kk * 16 + ((lane >> 3) & 1) * 8;
#pragma unroll
                for (int p = 0; p < 2; p++)
                    ldsm_x4(fb[p], bb + (uint32_t)(((row + p * 16) * KST + ko) * 2));
            }
#pragma unroll
            for (int mt = 0; mt < 4; mt++) {
#pragma unroll
                for (int p = 0; p < 2; p++) {
                    mma_fp16(acc[mt][2 * p],     fa[mt], fb[p][0], fb[p][1]);
                    mma_fp16(acc[mt][2 * p + 1], fa[mt], fb[p][2], fb[p][3]);
                }
            }
        }
        __syncthreads();
    }

#pragma unroll
    for (int mt = 0; mt < 4; mt++) {
        int row = bm + wr * 64 + mt * 16 + g;
#pragma unroll
        for (int nt = 0; nt < 4; nt++) {
            int col = bn + wc * 32 + nt * 8 + 2 * tg;
            float bx = bias[col], by = bias[col + 1];
            float v00 = acc[mt][nt][0] + bx, v01 = acc[mt][nt][1] + by;
            float v10 = acc[mt][nt][2] + bx, v11 = acc[mt][nt][3] + by;
            if (SPLIT_OUT) {
                uint32_t h0, l0, h1, l1;
                split2(v00, v01, h0, l0);
                split2(v10, v11, h1, l1);
                *(uint32_t*)&Ch[(size_t)row * N + col]       = h0;
                *(uint32_t*)&Cl[(size_t)row * N + col]       = l0;
                *(uint32_t*)&Ch[(size_t)(row + 8) * N + col] = h1;
                *(uint32_t*)&Cl[(size_t)(row + 8) * N + col] = l1;
            } else {
                *(float2*)&Cf[(size_t)row * N + col]       = make_float2(v00, v01);
                *(float2*)&Cf[(size_t)(row + 8) * N + col] = make_float2(v10, v11);
            }
        }
    }
}

// ============================================================
// Flash attention (3-term bf16 split): BM=64, 128 thr, 3 CTAs/SM,
// Q frags via LDG, K/V double-buffered cp.async. ctx out -> fp16.
// ============================================================
#define AST 72
#define STAGE_ELEMS (4 * 64 * AST)
#define ATT_SMEM_BYTES (2 * STAGE_ELEMS * 2)

__global__ __launch_bounds__(128, 3)
void flash_attn_v2(const __nv_bfloat16* __restrict__ qkvh,
                   const __nv_bfloat16* __restrict__ qkvl,
                   __half* __restrict__ ctxf)
{
    extern __shared__ __nv_bfloat16 sm[];

    const int h = blockIdx.y;
    const int qb = blockIdx.x;
    const int tid = threadIdx.x;
    const int w = tid >> 5, lane = tid & 31;
    const int g = lane >> 2, tg = lane & 3;

    const uint32_t smb = smaddr(sm);

    const size_t koff = DMODEL + (size_t)h * DH;
    const size_t voff = 2 * DMODEL + (size_t)h * DH;

    const int row0 = qb * 64 + w * 16;
    uint32_t qh[4][4], ql[4][4];
#pragma unroll
    for (int kk = 0; kk < 4; kk++) {
        size_t c = (size_t)h * DH + kk * 16 + 2 * tg;
        size_t rA = (size_t)(row0 + g) * QKVDIM + c;
        size_t rB = (size_t)(row0 + g + 8) * QKVDIM + c;
        qh[kk][0] = *(const uint32_t*)&qkvh[rA];
        qh[kk][1] = *(const uint32_t*)&qkvh[rB];
        qh[kk][2] = *(const uint32_t*)&qkvh[rA + 8];
        qh[kk][3] = *(const uint32_t*)&qkvh[rB + 8];
        ql[kk][0] = *(const uint32_t*)&qkvl[rA];
        ql[kk][1] = *(const uint32_t*)&qkvl[rB];
        ql[kk][2] = *(const uint32_t*)&qkvl[rA + 8];
        ql[kk][3] = *(const uint32_t*)&qkvl[rB + 8];
    }

    auto issue_kv = [&](int kt, int stage) {
        uint32_t base = smb + (uint32_t)(stage * STAGE_ELEMS) * 2;
        size_t rofs = (size_t)kt * 64 * QKVDIM;
#pragma unroll
        for (int i = 0; i < 4; i++) {
            int idx = tid + i * 128;
            int r = idx >> 3, c = idx & 7;
            uint32_t d = base + (uint32_t)(r * AST + c * 8) * 2;
            size_t srow = rofs + (size_t)r * QKVDIM + c * 8;
            CP16(d,                    qkvh + koff + srow);
            CP16(d + 64 * AST * 2,     qkvl + koff + srow);
            CP16(d + 2 * 64 * AST * 2, qkvh + voff + srow);
            CP16(d + 3 * 64 * AST * 2, qkvl + voff + srow);
        }
    };
    issue_kv(0, 0);
    CP_COMMIT();

    float m0 = -1e30f, m1 = -1e30f, l0 = 0.f, l1 = 0.f;
    float o[8][4];
#pragma unroll
    for (int t = 0; t < 8; t++)
#pragma unroll
        for (int c = 0; c < 4; c++) o[t][c] = 0.f;

    const int NT = SEQ / 64;
    for (int kt = 0; kt < NT; kt++) {
        if (kt + 1 < NT) {
            issue_kv(kt + 1, (kt + 1) & 1);
            CP_COMMIT();
            CP_WAIT1();
        } else {
            CP_WAIT0();
        }
        __syncthreads();

        uint32_t kb  = smb + (uint32_t)((kt & 1) * STAGE_ELEMS) * 2;
        uint32_t klb = kb + 64 * AST * 2;
        uint32_t vb  = kb + 2 * 64 * AST * 2;
        uint32_t vlb = kb + 3 * 64 * AST * 2;

        float s[8][4];
#pragma unroll
        for (int t = 0; t < 8; t++)
#pragma unroll
            for (int c = 0; c < 4; c++) s[t][c] = 0.f;

#pragma unroll
        for (int kk = 0; kk < 4; kk++) {
            int nrow = (lane & 7) + ((lane >> 4) << 3);
            int ko = kk * 16 + ((lane >> 3) & 1) * 8;
            uint32_t kbh[4][4], kbl2[4][4];
#pragma unroll
            for (int p = 0; p < 4; p++) {
                uint32_t off = (uint32_t)(((nrow + p * 16) * AST + ko) * 2);
                ldsm_x4(kbh[p], kb + off);
                ldsm_x4(kbl2[p], klb + off);
            }
#pragma unroll
            for (int p = 0; p < 4; p++) {
                mma_bf16(s[2 * p],     qh[kk], kbh[p][0], kbh[p][1]);
                mma_bf16(s[2 * p],     qh[kk], kbl2[p][0], kbl2[p][1]);
                mma_bf16(s[2 * p],     ql[kk], kbh[p][0], kbh[p][1]);
                mma_bf16(s[2 * p + 1], qh[kk], kbh[p][2], kbh[p][3]);
                mma_bf16(s[2 * p + 1], qh[kk], kbl2[p][2], kbl2[p][3]);
                mma_bf16(s[2 * p + 1], ql[kk], kbh[p][2], kbh[p][3]);
            }
        }
#pragma unroll
        for (int t = 0; t < 8; t++)
#pragma unroll
            for (int c = 0; c < 4; c++) s[t][c] *= 0.125f;

        {
            float mx = s[0][0];
#pragma unroll
            for (int t = 0; t < 8; t++) mx = fmaxf(mx, fmaxf(s[t][0], s[t][1]));
            mx = fmaxf(mx, __shfl_xor_sync(0xffffffffu, mx, 1));
            mx = fmaxf(mx, __shfl_xor_sync(0xffffffffu, mx, 2));
            float mn = fmaxf(m0, mx);
            float corr = __expf(m0 - mn);
            float sum = 0.f;
#pragma unroll
            for (int t = 0; t < 8; t++) {
                s[t][0] = __expf(s[t][0] - mn);
                s[t][1] = __expf(s[t][1] - mn);
                sum += s[t][0] + s[t][1];
            }
            sum += __shfl_xor_sync(0xffffffffu, sum, 1);
            sum += __shfl_xor_sync(0xffffffffu, sum, 2);
            l0 = l0 * corr + sum; m0 = mn;
#pragma unroll
            for (int t = 0; t < 8; t++) { o[t][0] *= corr; o[t][1] *= corr; }
        }
        {
            float mx = s[0][2];
#pragma unroll
            for (int t = 0; t < 8; t++) mx = fmaxf(mx, fmaxf(s[t][2], s[t][3]));
            mx = fmaxf(mx, __shfl_xor_sync(0xffffffffu, mx, 1));
            mx = fmaxf(mx, __shfl_xor_sync(0xffffffffu, mx, 2));
            float mn = fmaxf(m1, mx);
            float corr = __expf(m1 - mn);
            float sum = 0.f;
#pragma unroll
            for (int t = 0; t < 8; t++) {
                s[t][2] = __expf(s[t][2] - mn);
                s[t][3] = __expf(s[t][3] - mn);
                sum += s[t][2] + s[t][3];
            }
            sum += __shfl_xor_sync(0xffffffffu, sum, 1);
            sum += __shfl_xor_sync(0xffffffffu, sum, 2);
            l1 = l1 * corr + sum; m1 = mn;
#pragma unroll
            for (int t = 0; t < 8; t++) { o[t][2] *= corr; o[t][3] *= corr; }
        }

        uint32_t pah[4][4], pal[4][4];
#pragma unroll
        for (int t2 = 0; t2 < 4; t2++) {
            split2(s[2 * t2][0],     s[2 * t2][1],     pah[t2][0], pal[t2][0]);
            split2(s[2 * t2][2],     s[2 * t2][3],     pah[t2][1], pal[t2][1]);
            split2(s[2 * t2 + 1][0], s[2 * t2 + 1][1], pah[t2][2], pal[t2][2]);
            split2(s[2 * t2 + 1][2], s[2 * t2 + 1][3], pah[t2][3], pal[t2][3]);
        }

#pragma unroll
        for (int kk2 = 0; kk2 < 4; kk2++) {
            int krow = kk2 * 16 + (lane & 15);
            int no = (lane >> 4) * 8;
            uint32_t vbh[4][4], vbl2[4][4];
#pragma unroll
            for (int p = 0; p < 4; p++) {
                uint32_t off = (uint32_t)((krow * AST + p * 16 + no) * 2);
                ldsm_x4_t(vbh[p], vb + off);
                ldsm_x4_t(vbl2[p], vlb + off);
            }
#pragma unroll
            for (int p = 0; p < 4; p++) {
                mma_bf16(o[2 * p],     pah[kk2], vbh[p][0], vbh[p][1]);
                mma_bf16(o[2 * p],     pah[kk2], vbl2[p][0], vbl2[p][1]);
                mma_bf16(o[2 * p],     pal[kk2], vbh[p][0], vbh[p][1]);
                mma_bf16(o[2 * p + 1], pah[kk2], vbh[p][2], vbh[p][3]);
                mma_bf16(o[2 * p + 1], pah[kk2], vbl2[p][2], vbl2[p][3]);
                mma_bf16(o[2 * p + 1], pal[kk2], vbh[p][2], vbh[p][3]);
            }
        }
        __syncthreads();
    }

    // epilogue -> fp16 ctx
    float inv0 = 1.0f / l0, inv1 = 1.0f / l1;
#pragma unroll
    for (int t = 0; t < 8; t++) {
        int d = h * DH + 8 * t + 2 * tg;
        __half2 a = __float22half2_rn(make_float2(o[t][0] * inv0, o[t][1] * inv0));
        __half2 b = __float22half2_rn(make_float2(o[t][2] * inv1, o[t][3] * inv1));
        *(uint32_t*)&ctxf[(size_t)(row0 + g) * DMODEL + d]     = *(uint32_t*)&a;
        *(uint32_t*)&ctxf[(size_t)(row0 + g + 8) * DMODEL + d] = *(uint32_t*)&b;
    }
}

// ============================================================
extern "C" void kernel_launch(void* const* d_in, const int* in_sizes, int n_in,
                              void* d_out, int out_size)
{
    const float* x     = (const float*)d_in[0];
    const float* w_qkv = (const float*)d_in[1];
    const float* b_qkv = (const float*)d_in[2];
    const float* w_out = (const float*)d_in[3];
    const float* b_out = (const float*)d_in[4];
    float* out = (float*)d_out;

    __half *xf, *wqf, *wof, *ctxf;
    __nv_bfloat16 *qkvh, *qkvl;
    cudaGetSymbolAddress((void**)&xf, g_xf);
    cudaGetSymbolAddress((void**)&wqf, g_wqf);
    cudaGetSymbolAddress((void**)&wof, g_wof);
    cudaGetSymbolAddress((void**)&qkvh, g_qkvh);
    cudaGetSymbolAddress((void**)&qkvl, g_qkvl);
    cudaGetSymbolAddress((void**)&ctxf, g_ctxf);

    // 0) prepass: fp32 -> fp16
    {
        int n4;
        n4 = SEQ * DMODEL / 4;
        tohalf_kernel<<<(n4 + 255) / 256, 256>>>(x, xf, n4);
        n4 = QKVDIM * DMODEL / 4;
        tohalf_kernel<<<(n4 + 255) / 256, 256>>>(w_qkv, wqf, n4);
        n4 = DMODEL * DMODEL / 4;
        tohalf_kernel<<<(n4 + 255) / 256, 256>>>(w_out, wof, n4);
    }

    // 1) QKV projection (fp16 single-pass) -> split bf16 qkv
    {
        cudaFuncSetAttribute(gemm_fp16<true>,
                             cudaFuncAttributeMaxDynamicSharedMemorySize, HGEMM_SMEM_BYTES);
        dim3 grid(QKVDIM / 128, SEQ / 128);
        gemm_fp16<true><<<grid, 256, HGEMM_SMEM_BYTES>>>(
            xf, wqf, b_qkv, nullptr, qkvh, qkvl, SEQ, QKVDIM, DMODEL);
    }

    // 2) flash attention (3-term bf16) -> fp16 ctx
    {
        cudaFuncSetAttribute(flash_attn_v2,
                             cudaFuncAttributeMaxDynamicSharedMemorySize, ATT_SMEM_BYTES);
        dim3 grid(SEQ / 64, NHEADS);
        flash_attn_v2<<<grid, 128, ATT_SMEM_BYTES>>>(qkvh, qkvl, ctxf);
    }

    // 3) output projection (fp16 single-pass) -> fp32 out
    {
        cudaFuncSetAttribute(gemm_fp16<false>,
                             cudaFuncAttributeMaxDynamicSharedMemorySize, HGEMM_SMEM_BYTES);
        dim3 grid(DMODEL / 128, SEQ / 128);
        gemm_fp16<false><<<grid, 256, HGEMM_SMEM_BYTES>>>(
            ctxf, wof, b_out, out, nullptr, nullptr, SEQ, DMODEL, DMODEL);
    }
}

// round 7
// speedup vs baseline: 1.9113x; 1.3641x over previous
#include <cuda_runtime.h>
#include <cuda_bf16.h>
#include <cuda_fp16.h>
#include <cstdint>

#define SEQ     4096
#define DMODEL  1024
#define NHEADS  16
#define DH      64
#define QKVDIM  (3 * DMODEL)

// ---------------- scratch ----------------
__device__ __half g_xf[(size_t)SEQ * DMODEL];
__device__ __half g_wqf[(size_t)QKVDIM * DMODEL];
__device__ __half g_wof[(size_t)DMODEL * DMODEL];
__device__ __half g_qkvf[(size_t)SEQ * QKVDIM];    // fp16(acc)
__device__ __half g_qkvfl[(size_t)SEQ * QKVDIM];   // fp16(acc - hi)
__device__ __half g_ctxf[(size_t)SEQ * DMODEL];

// ============================================================
// helpers
// ============================================================
__device__ __forceinline__ uint32_t smaddr(const void* p) {
    return static_cast<uint32_t>(__cvta_generic_to_shared(p));
}
__device__ __forceinline__ void split2h(float x, float y, uint32_t& hi, uint32_t& lo) {
    __half2 h = __float22half2_rn(make_float2(x, y));
    float2 hf = __half22float2(h);
    __half2 l = __float22half2_rn(make_float2(x - hf.x, y - hf.y));
    hi = *reinterpret_cast<uint32_t*>(&h);
    lo = *reinterpret_cast<uint32_t*>(&l);
}
__device__ __forceinline__ void ldsm_x4(uint32_t* r, uint32_t addr) {
    asm volatile("ldmatrix.sync.aligned.m8n8.x4.shared.b16 {%0,%1,%2,%3}, [%4];"
                 : "=r"(r[0]), "=r"(r[1]), "=r"(r[2]), "=r"(r[3]) : "r"(addr));
}
__device__ __forceinline__ void ldsm_x4_t(uint32_t* r, uint32_t addr) {
    asm volatile("ldmatrix.sync.aligned.m8n8.x4.trans.shared.b16 {%0,%1,%2,%3}, [%4];"
                 : "=r"(r[0]), "=r"(r[1]), "=r"(r[2]), "=r"(r[3]) : "r"(addr));
}
__device__ __forceinline__ void mma_fp16(float* d, const uint32_t* a, uint32_t b0, uint32_t b1) {
    asm volatile(
        "mma.sync.aligned.m16n8k16.row.col.f32.f16.f16.f32 "
        "{%0,%1,%2,%3}, {%4,%5,%6,%7}, {%8,%9}, {%0,%1,%2,%3};"
        : "+f"(d[0]), "+f"(d[1]), "+f"(d[2]), "+f"(d[3])
        : "r"(a[0]), "r"(a[1]), "r"(a[2]), "r"(a[3]), "r"(b0), "r"(b1));
}
#define CP16(dst, src) asm volatile("cp.async.cg.shared.global [%0], [%1], 16;" :: "r"(dst), "l"(src))
#define CP_COMMIT()    asm volatile("cp.async.commit_group;")
#define CP_WAIT1()     asm volatile("cp.async.wait_group 1;")
#define CP_WAIT0()     asm volatile("cp.async.wait_group 0;")

// ============================================================
// prepass: fp32 -> fp16
// ============================================================
__global__ void tohalf_kernel(const float* __restrict__ in,
                              __half* __restrict__ o, int n4)
{
    int i = blockIdx.x * blockDim.x + threadIdx.x;
    if (i >= n4) return;
    float4 v = ((const float4*)in)[i];
    __half2 a = __float22half2_rn(make_float2(v.x, v.y));
    __half2 b = __float22half2_rn(make_float2(v.z, v.w));
    ((uint2*)o)[i] = make_uint2(*(uint32_t*)&a, *(uint32_t*)&b);
}

// ============================================================
// fp16 single-pass GEMM: C[M,N] = A[M,K]*B[N,K]^T + bias
// SPLIT_OUT: write fp16 hi + fp16 lo (residual), else fp32.
// ============================================================
#define KST 40
#define HSTAGE (2 * 128 * KST)
#define HGEMM_SMEM_BYTES (2 * HSTAGE * 2)

template <bool SPLIT_OUT>
__global__ __launch_bounds__(256)
void gemm_fp16(const __half* __restrict__ A, const __half* __restrict__ B,
               const float* __restrict__ bias,
               float* __restrict__ Cf,
               __half* __restrict__ Ch, __half* __restrict__ Cl,
               int M, int N, int K)
{
    extern __shared__ __half hsm[];

    const int tid = threadIdx.x;
    const int w = tid >> 5, lane = tid & 31;
    const int wr = w >> 2, wc = w & 3;
    const int g = lane >> 2, tg = lane & 3;
    const int bm = blockIdx.y * 128, bn = blockIdx.x * 128;

    const uint32_t smb = smaddr(hsm);

    float acc[4][4][4];
#pragma unroll
    for (int a = 0; a < 4; a++)
#pragma unroll
        for (int b = 0; b < 4; b++)
#pragma unroll
            for (int c = 0; c < 4; c++) acc[a][b][c] = 0.f;

    auto issue_stage = [&](int kt, int stage) {
        const size_t ko = (size_t)kt * 32;
        uint32_t base = smb + (uint32_t)stage * HSTAGE * 2;
#pragma unroll
        for (int i = 0; i < 2; i++) {
            int idx = tid + i * 256;
            int r = idx >> 2, c = idx & 3;
            uint32_t d = base + (uint32_t)(r * KST + c * 8) * 2;
            CP16(d,                 A + (size_t)(bm + r) * K + ko + c * 8);
            CP16(d + 128 * KST * 2, B + (size_t)(bn + r) * K + ko + c * 8);
        }
    };

    const int nsteps = K >> 5;
    issue_stage(0, 0);
    CP_COMMIT();

    for (int kt = 0; kt < nsteps; kt++) {
        if (kt + 1 < nsteps) {
            issue_stage(kt + 1, (kt + 1) & 1);
            CP_COMMIT();
            CP_WAIT1();
        } else {
            CP_WAIT0();
        }
        __syncthreads();

        uint32_t ab = smb + (uint32_t)(kt & 1) * HSTAGE * 2;
        uint32_t bb = ab + 128 * KST * 2;

#pragma unroll
        for (int kk = 0; kk < 2; kk++) {
            uint32_t fa[4][4];
            {
                int row = wr * 64 + (lane & 15);
                int ko = kk * 16 + (lane >> 4) * 8;
#pragma unroll
                for (int mt = 0; mt < 4; mt++)
                    ldsm_x4(fa[mt], ab + (uint32_t)(((row + mt * 16) * KST + ko) * 2));
            }
            uint32_t fb[2][4];
            {
                int row = wc * 32 + (lane & 7) + ((lane >> 4) << 3);
                int ko = kk * 16 + ((lane >> 3) & 1) * 8;
#pragma unroll
                for (int p = 0; p < 2; p++)
                    ldsm_x4(fb[p], bb + (uint32_t)(((row + p * 16) * KST + ko) * 2));
            }
#pragma unroll
            for (int mt = 0; mt < 4; mt++) {
#pragma unroll
                for (int p = 0; p < 2; p++) {
                    mma_fp16(acc[mt][2 * p],     fa[mt], fb[p][0], fb[p][1]);
                    mma_fp16(acc[mt][2 * p + 1], fa[mt], fb[p][2], fb[p][3]);
                }
            }
        }
        __syncthreads();
    }

#pragma unroll
    for (int mt = 0; mt < 4; mt++) {
        int row = bm + wr * 64 + mt * 16 + g;
#pragma unroll
        for (int nt = 0; nt < 4; nt++) {
            int col = bn + wc * 32 + nt * 8 + 2 * tg;
            float bx = bias[col], by = bias[col + 1];
            float v00 = acc[mt][nt][0] + bx, v01 = acc[mt][nt][1] + by;
            float v10 = acc[mt][nt][2] + bx, v11 = acc[mt][nt][3] + by;
            if (SPLIT_OUT) {
                uint32_t h0, l0, h1, l1;
                split2h(v00, v01, h0, l0);
                split2h(v10, v11, h1, l1);
                *(uint32_t*)&Ch[(size_t)row * N + col]       = h0;
                *(uint32_t*)&Cl[(size_t)row * N + col]       = l0;
                *(uint32_t*)&Ch[(size_t)(row + 8) * N + col] = h1;
                *(uint32_t*)&Cl[(size_t)(row + 8) * N + col] = l1;
            } else {
                *(float2*)&Cf[(size_t)row * N + col]       = make_float2(v00, v01);
                *(float2*)&Cf[(size_t)(row + 8) * N + col] = make_float2(v10, v11);
            }
        }
    }
}

// ============================================================
// Flash attention v3 (fp16): Q 2-term fp16 (regs), K/V single fp16,
// P 2-term fp16. BM=64, 128 thr, K/V double-buffered cp.async.
// ============================================================
#define AST 72
#define KV_STAGE (2 * 64 * AST)                 // Kf, Vf (fp16 elems)
#define ATT_SMEM_BYTES (2 * KV_STAGE * 2)       // 36864

__global__ __launch_bounds__(128, 3)
void flash_attn_v3(const __half* __restrict__ qkvf,
                   const __half* __restrict__ qkvfl,
                   __half* __restrict__ ctxf)
{
    extern __shared__ __half sm[];

    const int h = blockIdx.y;
    const int qb = blockIdx.x;
    const int tid = threadIdx.x;
    const int w = tid >> 5, lane = tid & 31;
    const int g = lane >> 2, tg = lane & 3;

    const uint32_t smb = smaddr(sm);

    const size_t koff = DMODEL + (size_t)h * DH;
    const size_t voff = 2 * DMODEL + (size_t)h * DH;

    // ---- Q fragments (hi/lo fp16) via direct LDG ----
    const int row0 = qb * 64 + w * 16;
    uint32_t qh[4][4], ql[4][4];
#pragma unroll
    for (int kk = 0; kk < 4; kk++) {
        size_t c = (size_t)h * DH + kk * 16 + 2 * tg;
        size_t rA = (size_t)(row0 + g) * QKVDIM + c;
        size_t rB = (size_t)(row0 + g + 8) * QKVDIM + c;
        qh[kk][0] = *(const uint32_t*)&qkvf[rA];
        qh[kk][1] = *(const uint32_t*)&qkvf[rB];
        qh[kk][2] = *(const uint32_t*)&qkvf[rA + 8];
        qh[kk][3] = *(const uint32_t*)&qkvf[rB + 8];
        ql[kk][0] = *(const uint32_t*)&qkvfl[rA];
        ql[kk][1] = *(const uint32_t*)&qkvfl[rB];
        ql[kk][2] = *(const uint32_t*)&qkvfl[rA + 8];
        ql[kk][3] = *(const uint32_t*)&qkvfl[rB + 8];
    }

    // ---- K/V stage fill (single fp16, 2 buffers) ----
    auto issue_kv = [&](int kt, int stage) {
        uint32_t base = smb + (uint32_t)(stage * KV_STAGE) * 2;
        size_t rofs = (size_t)kt * 64 * QKVDIM;
#pragma unroll
        for (int i = 0; i < 4; i++) {
            int idx = tid + i * 128;      // 512: 64 rows x 8 chunks
            int r = idx >> 3, c = idx & 7;
            uint32_t d = base + (uint32_t)(r * AST + c * 8) * 2;
            size_t srow = rofs + (size_t)r * QKVDIM + c * 8;
            CP16(d,                qkvf + koff + srow);
            CP16(d + 64 * AST * 2, qkvf + voff + srow);
        }
    };
    issue_kv(0, 0);
    CP_COMMIT();

    float m0 = -1e30f, m1 = -1e30f, l0 = 0.f, l1 = 0.f;
    float o[8][4];
#pragma unroll
    for (int t = 0; t < 8; t++)
#pragma unroll
        for (int c = 0; c < 4; c++) o[t][c] = 0.f;

    const int NT = SEQ / 64;
    for (int kt = 0; kt < NT; kt++) {
        if (kt + 1 < NT) {
            issue_kv(kt + 1, (kt + 1) & 1);
            CP_COMMIT();
            CP_WAIT1();
        } else {
            CP_WAIT0();
        }
        __syncthreads();

        uint32_t kb = smb + (uint32_t)((kt & 1) * KV_STAGE) * 2;
        uint32_t vb = kb + 64 * AST * 2;

        // ---- S = Q K^T : (qh+ql) x Kf, 2 MMAs per fragment-pair ----
        float s[8][4];
#pragma unroll
        for (int t = 0; t < 8; t++)
#pragma unroll
            for (int c = 0; c < 4; c++) s[t][c] = 0.f;

#pragma unroll
        for (int kk = 0; kk < 4; kk++) {
            int nrow = (lane & 7) + ((lane >> 4) << 3);
            int ko = kk * 16 + ((lane >> 3) & 1) * 8;
            uint32_t kf[4][4];
#pragma unroll
            for (int p = 0; p < 4; p++)
                ldsm_x4(kf[p], kb + (uint32_t)(((nrow + p * 16) * AST + ko) * 2));
#pragma unroll
            for (int p = 0; p < 4; p++) {
                mma_fp16(s[2 * p],     qh[kk], kf[p][0], kf[p][1]);
                mma_fp16(s[2 * p],     ql[kk], kf[p][0], kf[p][1]);
                mma_fp16(s[2 * p + 1], qh[kk], kf[p][2], kf[p][3]);
                mma_fp16(s[2 * p + 1], ql[kk], kf[p][2], kf[p][3]);
            }
        }
#pragma unroll
        for (int t = 0; t < 8; t++)
#pragma unroll
            for (int c = 0; c < 4; c++) s[t][c] *= 0.125f;

        // ---- online softmax ----
        {
            float mx = s[0][0];
#pragma unroll
            for (int t = 0; t < 8; t++) mx = fmaxf(mx, fmaxf(s[t][0], s[t][1]));
            mx = fmaxf(mx, __shfl_xor_sync(0xffffffffu, mx, 1));
            mx = fmaxf(mx, __shfl_xor_sync(0xffffffffu, mx, 2));
            float mn = fmaxf(m0, mx);
            float corr = __expf(m0 - mn);
            float sum = 0.f;
#pragma unroll
            for (int t = 0; t < 8; t++) {
                s[t][0] = __expf(s[t][0] - mn);
                s[t][1] = __expf(s[t][1] - mn);
                sum += s[t][0] + s[t][1];
            }
            sum += __shfl_xor_sync(0xffffffffu, sum, 1);
            sum += __shfl_xor_sync(0xffffffffu, sum, 2);
            l0 = l0 * corr + sum; m0 = mn;
#pragma unroll
            for (int t = 0; t < 8; t++) { o[t][0] *= corr; o[t][1] *= corr; }
        }
        {
            float mx = s[0][2];
#pragma unroll
            for (int t = 0; t < 8; t++) mx = fmaxf(mx, fmaxf(s[t][2], s[t][3]));
            mx = fmaxf(mx, __shfl_xor_sync(0xffffffffu, mx, 1));
            mx = fmaxf(mx, __shfl_xor_sync(0xffffffffu, mx, 2));
            float mn = fmaxf(m1, mx);
            float corr = __expf(m1 - mn);
            float sum = 0.f;
#pragma unroll
            for (int t = 0; t < 8; t++) {
                s[t][2] = __expf(s[t][2] - mn);
                s[t][3] = __expf(s[t][3] - mn);
                sum += s[t][2] + s[t][3];
            }
            sum += __shfl_xor_sync(0xffffffffu, sum, 1);
            sum += __shfl_xor_sync(0xffffffffu, sum, 2);
            l1 = l1 * corr + sum; m1 = mn;
#pragma unroll
            for (int t = 0; t < 8; t++) { o[t][2] *= corr; o[t][3] *= corr; }
        }

        // ---- pack P (hi/lo fp16) ----
        uint32_t pah[4][4], pal[4][4];
#pragma unroll
        for (int t2 = 0; t2 < 4; t2++) {
            split2h(s[2 * t2][0],     s[2 * t2][1],     pah[t2][0], pal[t2][0]);
            split2h(s[2 * t2][2],     s[2 * t2][3],     pah[t2][1], pal[t2][1]);
            split2h(s[2 * t2 + 1][0], s[2 * t2 + 1][1], pah[t2][2], pal[t2][2]);
            split2h(s[2 * t2 + 1][2], s[2 * t2 + 1][3], pah[t2][3], pal[t2][3]);
        }

        // ---- O += (Ph+Pl) V ----
#pragma unroll
        for (int kk2 = 0; kk2 < 4; kk2++) {
            int krow = kk2 * 16 + (lane & 15);
            int no = (lane >> 4) * 8;
            uint32_t vf[4][4];
#pragma unroll
            for (int p = 0; p < 4; p++)
                ldsm_x4_t(vf[p], vb + (uint32_t)((krow * AST + p * 16 + no) * 2));
#pragma unroll
            for (int p = 0; p < 4; p++) {
                mma_fp16(o[2 * p],     pah[kk2], vf[p][0], vf[p][1]);
                mma_fp16(o[2 * p],     pal[kk2], vf[p][0], vf[p][1]);
                mma_fp16(o[2 * p + 1], pah[kk2], vf[p][2], vf[p][3]);
                mma_fp16(o[2 * p + 1], pal[kk2], vf[p][2], vf[p][3]);
            }
        }
        __syncthreads();
    }

    // ---- epilogue -> fp16 ctx ----
    float inv0 = 1.0f / l0, inv1 = 1.0f / l1;
#pragma unroll
    for (int t = 0; t < 8; t++) {
        int d = h * DH + 8 * t + 2 * tg;
        __half2 a = __float22half2_rn(make_float2(o[t][0] * inv0, o[t][1] * inv0));
        __half2 b = __float22half2_rn(make_float2(o[t][2] * inv1, o[t][3] * inv1));
        *(uint32_t*)&ctxf[(size_t)(row0 + g) * DMODEL + d]     = *(uint32_t*)&a;
        *(uint32_t*)&ctxf[(size_t)(row0 + g + 8) * DMODEL + d] = *(uint32_t*)&b;
    }
}

// ============================================================
extern "C" void kernel_launch(void* const* d_in, const int* in_sizes, int n_in,
                              void* d_out, int out_size)
{
    const float* x     = (const float*)d_in[0];
    const float* w_qkv = (const float*)d_in[1];
    const float* b_qkv = (const float*)d_in[2];
    const float* w_out = (const float*)d_in[3];
    const float* b_out = (const float*)d_in[4];
    float* out = (float*)d_out;

    __half *xf, *wqf, *wof, *qkvf, *qkvfl, *ctxf;
    cudaGetSymbolAddress((void**)&xf, g_xf);
    cudaGetSymbolAddress((void**)&wqf, g_wqf);
    cudaGetSymbolAddress((void**)&wof, g_wof);
    cudaGetSymbolAddress((void**)&qkvf, g_qkvf);
    cudaGetSymbolAddress((void**)&qkvfl, g_qkvfl);
    cudaGetSymbolAddress((void**)&ctxf, g_ctxf);

    // 0) prepass: fp32 -> fp16
    {
        int n4;
        n4 = SEQ * DMODEL / 4;
        tohalf_kernel<<<(n4 + 255) / 256, 256>>>(x, xf, n4);
        n4 = QKVDIM * DMODEL / 4;
        tohalf_kernel<<<(n4 + 255) / 256, 256>>>(w_qkv, wqf, n4);
        n4 = DMODEL * DMODEL / 4;
        tohalf_kernel<<<(n4 + 255) / 256, 256>>>(w_out, wof, n4);
    }

    // 1) QKV projection -> fp16 hi/lo qkv
    {
        cudaFuncSetAttribute(gemm_fp16<true>,
                             cudaFuncAttributeMaxDynamicSharedMemorySize, HGEMM_SMEM_BYTES);
        dim3 grid(QKVDIM / 128, SEQ / 128);
        gemm_fp16<true><<<grid, 256, HGEMM_SMEM_BYTES>>>(
            xf, wqf, b_qkv, nullptr, qkvf, qkvfl, SEQ, QKVDIM, DMODEL);
    }

    // 2) flash attention -> fp16 ctx
    {
        cudaFuncSetAttribute(flash_attn_v3,
                             cudaFuncAttributeMaxDynamicSharedMemorySize, ATT_SMEM_BYTES);
        dim3 grid(SEQ / 64, NHEADS);
        flash_attn_v3<<<grid, 128, ATT_SMEM_BYTES>>>(qkvf, qkvfl, ctxf);
    }

    // 3) output projection -> fp32 out
    {
        cudaFuncSetAttribute(gemm_fp16<false>,
                             cudaFuncAttributeMaxDynamicSharedMemorySize, HGEMM_SMEM_BYTES);
        dim3 grid(DMODEL / 128, SEQ / 128);
        gemm_fp16<false><<<grid, 256, HGEMM_SMEM_BYTES>>>(
            ctxf, wof, b_out, out, nullptr, nullptr, SEQ, DMODEL, DMODEL);
    }
}

// round 8
// speedup vs baseline: 2.5315x; 1.3245x over previous
#include <cuda_runtime.h>
#include <cuda_fp16.h>
#include <cstdint>

#define SEQ     4096
#define DMODEL  1024
#define NHEADS  16
#define DH      64
#define QKVDIM  (3 * DMODEL)

// ---------------- scratch ----------------
__device__ __half g_xf[(size_t)SEQ * DMODEL];
__device__ __half g_wqf[(size_t)QKVDIM * DMODEL];
__device__ __half g_wof[(size_t)DMODEL * DMODEL];
__device__ __half g_qkvf[(size_t)SEQ * QKVDIM];
__device__ __half g_ctxf[(size_t)SEQ * DMODEL];

// ============================================================
// helpers
// ============================================================
__device__ __forceinline__ uint32_t smaddr(const void* p) {
    return static_cast<uint32_t>(__cvta_generic_to_shared(p));
}
__device__ __forceinline__ uint32_t h2u(__half2 v) {
    return *reinterpret_cast<uint32_t*>(&v);
}
__device__ __forceinline__ void ldsm_x4(uint32_t* r, uint32_t addr) {
    asm volatile("ldmatrix.sync.aligned.m8n8.x4.shared.b16 {%0,%1,%2,%3}, [%4];"
                 : "=r"(r[0]), "=r"(r[1]), "=r"(r[2]), "=r"(r[3]) : "r"(addr));
}
__device__ __forceinline__ void ldsm_x4_t(uint32_t* r, uint32_t addr) {
    asm volatile("ldmatrix.sync.aligned.m8n8.x4.trans.shared.b16 {%0,%1,%2,%3}, [%4];"
                 : "=r"(r[0]), "=r"(r[1]), "=r"(r[2]), "=r"(r[3]) : "r"(addr));
}
__device__ __forceinline__ void mma_fp16(float* d, const uint32_t* a, uint32_t b0, uint32_t b1) {
    asm volatile(
        "mma.sync.aligned.m16n8k16.row.col.f32.f16.f16.f32 "
        "{%0,%1,%2,%3}, {%4,%5,%6,%7}, {%8,%9}, {%0,%1,%2,%3};"
        : "+f"(d[0]), "+f"(d[1]), "+f"(d[2]), "+f"(d[3])
        : "r"(a[0]), "r"(a[1]), "r"(a[2]), "r"(a[3]), "r"(b0), "r"(b1));
}
#define CP16(dst, src) asm volatile("cp.async.cg.shared.global [%0], [%1], 16;" :: "r"(dst), "l"(src))
#define CP_COMMIT()    asm volatile("cp.async.commit_group;")
#define CP_WAIT1()     asm volatile("cp.async.wait_group 1;")
#define CP_WAIT0()     asm volatile("cp.async.wait_group 0;")

// ============================================================
// prepass: fp32 -> fp16
// ============================================================
__global__ void tohalf_kernel(const float* __restrict__ in,
                              __half* __restrict__ o, int n4)
{
    int i = blockIdx.x * blockDim.x + threadIdx.x;
    if (i >= n4) return;
    float4 v = ((const float4*)in)[i];
    __half2 a = __float22half2_rn(make_float2(v.x, v.y));
    __half2 b = __float22half2_rn(make_float2(v.z, v.w));
    ((uint2*)o)[i] = make_uint2(h2u(a), h2u(b));
}

// ============================================================
// fp16 single-pass GEMM: C[M,N] = A[M,K]*B[N,K]^T + bias
// HALF_OUT: write fp16, else fp32.
// ============================================================
#define KST 40
#define HSTAGE (2 * 128 * KST)
#define HGEMM_SMEM_BYTES (2 * HSTAGE * 2)

template <bool HALF_OUT>
__global__ __launch_bounds__(256)
void gemm_fp16(const __half* __restrict__ A, const __half* __restrict__ B,
               const float* __restrict__ bias,
               float* __restrict__ Cf, __half* __restrict__ Ch,
               int M, int N, int K)
{
    extern __shared__ __half hsm[];

    const int tid = threadIdx.x;
    const int w = tid >> 5, lane = tid & 31;
    const int wr = w >> 2, wc = w & 3;
    const int g = lane >> 2, tg = lane & 3;
    const int bm = blockIdx.y * 128, bn = blockIdx.x * 128;

    const uint32_t smb = smaddr(hsm);

    float acc[4][4][4];
#pragma unroll
    for (int a = 0; a < 4; a++)
#pragma unroll
        for (int b = 0; b < 4; b++)
#pragma unroll
            for (int c = 0; c < 4; c++) acc[a][b][c] = 0.f;

    auto issue_stage = [&](int kt, int stage) {
        const size_t ko = (size_t)kt * 32;
        uint32_t base = smb + (uint32_t)stage * HSTAGE * 2;
#pragma unroll
        for (int i = 0; i < 2; i++) {
            int idx = tid + i * 256;
            int r = idx >> 2, c = idx & 3;
            uint32_t d = base + (uint32_t)(r * KST + c * 8) * 2;
            CP16(d,                 A + (size_t)(bm + r) * K + ko + c * 8);
            CP16(d + 128 * KST * 2, B + (size_t)(bn + r) * K + ko + c * 8);
        }
    };

    const int nsteps = K >> 5;
    issue_stage(0, 0);
    CP_COMMIT();

    for (int kt = 0; kt < nsteps; kt++) {
        if (kt + 1 < nsteps) {
            issue_stage(kt + 1, (kt + 1) & 1);
            CP_COMMIT();
            CP_WAIT1();
        } else {
            CP_WAIT0();
        }
        __syncthreads();

        uint32_t ab = smb + (uint32_t)(kt & 1) * HSTAGE * 2;
        uint32_t bb = ab + 128 * KST * 2;

#pragma unroll
        for (int kk = 0; kk < 2; kk++) {
            uint32_t fa[4][4];
            {
                int row = wr * 64 + (lane & 15);
                int ko = kk * 16 + (lane >> 4) * 8;
#pragma unroll
                for (int mt = 0; mt < 4; mt++)
                    ldsm_x4(fa[mt], ab + (uint32_t)(((row + mt * 16) * KST + ko) * 2));
            }
            uint32_t fb[2][4];
            {
                int row = wc * 32 + (lane & 7) + ((lane >> 4) << 3);
                int ko = kk * 16 + ((lane >> 3) & 1) * 8;
#pragma unroll
                for (int p = 0; p < 2; p++)
                    ldsm_x4(fb[p], bb + (uint32_t)(((row + p * 16) * KST + ko) * 2));
            }
#pragma unroll
            for (int mt = 0; mt < 4; mt++) {
#pragma unroll
                for (int p = 0; p < 2; p++) {
                    mma_fp16(acc[mt][2 * p],     fa[mt], fb[p][0], fb[p][1]);
                    mma_fp16(acc[mt][2 * p + 1], fa[mt], fb[p][2], fb[p][3]);
                }
            }
        }
        __syncthreads();
    }

#pragma unroll
    for (int mt = 0; mt < 4; mt++) {
        int row = bm + wr * 64 + mt * 16 + g;
#pragma unroll
        for (int nt = 0; nt < 4; nt++) {
            int col = bn + wc * 32 + nt * 8 + 2 * tg;
            float bx = bias[col], by = bias[col + 1];
            float v00 = acc[mt][nt][0] + bx, v01 = acc[mt][nt][1] + by;
            float v10 = acc[mt][nt][2] + bx, v11 = acc[mt][nt][3] + by;
            if (HALF_OUT) {
                __half2 a = __float22half2_rn(make_float2(v00, v01));
                __half2 b = __float22half2_rn(make_float2(v10, v11));
                *(uint32_t*)&Ch[(size_t)row * N + col]       = h2u(a);
                *(uint32_t*)&Ch[(size_t)(row + 8) * N + col] = h2u(b);
            } else {
                *(float2*)&Cf[(size_t)row * N + col]       = make_float2(v00, v01);
                *(float2*)&Cf[(size_t)(row + 8) * N + col] = make_float2(v10, v11);
            }
        }
    }
}

// ============================================================
// Flash attention v4: all-single-fp16 Q,K,V,P.
// BM=64, 128 thr, 4 CTAs/SM, K/V double-buffered cp.async.
// ============================================================
#define AST 72
#define KV_STAGE (2 * 64 * AST)
#define ATT_SMEM_BYTES (2 * KV_STAGE * 2)       // 36864

__global__ __launch_bounds__(128, 4)
void flash_attn_v4(const __half* __restrict__ qkvf, __half* __restrict__ ctxf)
{
    extern __shared__ __half sm[];

    const int h = blockIdx.y;
    const int qb = blockIdx.x;
    const int tid = threadIdx.x;
    const int w = tid >> 5, lane = tid & 31;
    const int g = lane >> 2, tg = lane & 3;

    const uint32_t smb = smaddr(sm);

    const size_t koff = DMODEL + (size_t)h * DH;
    const size_t voff = 2 * DMODEL + (size_t)h * DH;

    // ---- Q fragments via direct LDG ----
    const int row0 = qb * 64 + w * 16;
    uint32_t qf[4][4];
#pragma unroll
    for (int kk = 0; kk < 4; kk++) {
        size_t c = (size_t)h * DH + kk * 16 + 2 * tg;
        size_t rA = (size_t)(row0 + g) * QKVDIM + c;
        size_t rB = (size_t)(row0 + g + 8) * QKVDIM + c;
        qf[kk][0] = *(const uint32_t*)&qkvf[rA];
        qf[kk][1] = *(const uint32_t*)&qkvf[rB];
        qf[kk][2] = *(const uint32_t*)&qkvf[rA + 8];
        qf[kk][3] = *(const uint32_t*)&qkvf[rB + 8];
    }

    auto issue_kv = [&](int kt, int stage) {
        uint32_t base = smb + (uint32_t)(stage * KV_STAGE) * 2;
        size_t rofs = (size_t)kt * 64 * QKVDIM;
#pragma unroll
        for (int i = 0; i < 4; i++) {
            int idx = tid + i * 128;
            int r = idx >> 3, c = idx & 7;
            uint32_t d = base + (uint32_t)(r * AST + c * 8) * 2;
            size_t srow = rofs + (size_t)r * QKVDIM + c * 8;
            CP16(d,                qkvf + koff + srow);
            CP16(d + 64 * AST * 2, qkvf + voff + srow);
        }
    };
    issue_kv(0, 0);
    CP_COMMIT();

    float m0 = -1e30f, m1 = -1e30f, l0 = 0.f, l1 = 0.f;
    float o[8][4];
#pragma unroll
    for (int t = 0; t < 8; t++)
#pragma unroll
        for (int c = 0; c < 4; c++) o[t][c] = 0.f;

    const int NT = SEQ / 64;
    for (int kt = 0; kt < NT; kt++) {
        if (kt + 1 < NT) {
            issue_kv(kt + 1, (kt + 1) & 1);
            CP_COMMIT();
            CP_WAIT1();
        } else {
            CP_WAIT0();
        }
        __syncthreads();

        uint32_t kb = smb + (uint32_t)((kt & 1) * KV_STAGE) * 2;
        uint32_t vb = kb + 64 * AST * 2;

        // ---- S = Q K^T ----
        float s[8][4];
#pragma unroll
        for (int t = 0; t < 8; t++)
#pragma unroll
            for (int c = 0; c < 4; c++) s[t][c] = 0.f;

#pragma unroll
        for (int kk = 0; kk < 4; kk++) {
            int nrow = (lane & 7) + ((lane >> 4) << 3);
            int ko = kk * 16 + ((lane >> 3) & 1) * 8;
            uint32_t kf[4][4];
#pragma unroll
            for (int p = 0; p < 4; p++)
                ldsm_x4(kf[p], kb + (uint32_t)(((nrow + p * 16) * AST + ko) * 2));
#pragma unroll
            for (int p = 0; p < 4; p++) {
                mma_fp16(s[2 * p],     qf[kk], kf[p][0], kf[p][1]);
                mma_fp16(s[2 * p + 1], qf[kk], kf[p][2], kf[p][3]);
            }
        }
#pragma unroll
        for (int t = 0; t < 8; t++)
#pragma unroll
            for (int c = 0; c < 4; c++) s[t][c] *= 0.125f;

        // ---- online softmax ----
        {
            float mx = s[0][0];
#pragma unroll
            for (int t = 0; t < 8; t++) mx = fmaxf(mx, fmaxf(s[t][0], s[t][1]));
            mx = fmaxf(mx, __shfl_xor_sync(0xffffffffu, mx, 1));
            mx = fmaxf(mx, __shfl_xor_sync(0xffffffffu, mx, 2));
            float mn = fmaxf(m0, mx);
            float corr = __expf(m0 - mn);
            float sum = 0.f;
#pragma unroll
            for (int t = 0; t < 8; t++) {
                s[t][0] = __expf(s[t][0] - mn);
                s[t][1] = __expf(s[t][1] - mn);
                sum += s[t][0] + s[t][1];
            }
            sum += __shfl_xor_sync(0xffffffffu, sum, 1);
            sum += __shfl_xor_sync(0xffffffffu, sum, 2);
            l0 = l0 * corr + sum; m0 = mn;
#pragma unroll
            for (int t = 0; t < 8; t++) { o[t][0] *= corr; o[t][1] *= corr; }
        }
        {
            float mx = s[0][2];
#pragma unroll
            for (int t = 0; t < 8; t++) mx = fmaxf(mx, fmaxf(s[t][2], s[t][3]));
            mx = fmaxf(mx, __shfl_xor_sync(0xffffffffu, mx, 1));
            mx = fmaxf(mx, __shfl_xor_sync(0xffffffffu, mx, 2));
            float mn = fmaxf(m1, mx);
            float corr = __expf(m1 - mn);
            float sum = 0.f;
#pragma unroll
            for (int t = 0; t < 8; t++) {
                s[t][2] = __expf(s[t][2] - mn);
                s[t][3] = __expf(s[t][3] - mn);
                sum += s[t][2] + s[t][3];
            }
            sum += __shfl_xor_sync(0xffffffffu, sum, 1);
            sum += __shfl_xor_sync(0xffffffffu, sum, 2);
            l1 = l1 * corr + sum; m1 = mn;
#pragma unroll
            for (int t = 0; t < 8; t++) { o[t][2] *= corr; o[t][3] *= corr; }
        }

        // ---- pack P (single fp16) ----
        uint32_t pa[4][4];
#pragma unroll
        for (int t2 = 0; t2 < 4; t2++) {
            pa[t2][0] = h2u(__float22half2_rn(make_float2(s[2 * t2][0],     s[2 * t2][1])));
            pa[t2][1] = h2u(__float22half2_rn(make_float2(s[2 * t2][2],     s[2 * t2][3])));
            pa[t2][2] = h2u(__float22half2_rn(make_float2(s[2 * t2 + 1][0], s[2 * t2 + 1][1])));
            pa[t2][3] = h2u(__float22half2_rn(make_float2(s[2 * t2 + 1][2], s[2 * t2 + 1][3])));
        }

        // ---- O += P V ----
#pragma unroll
        for (int kk2 = 0; kk2 < 4; kk2++) {
            int krow = kk2 * 16 + (lane & 15);
            int no = (lane >> 4) * 8;
            uint32_t vf[4][4];
#pragma unroll
            for (int p = 0; p < 4; p++)
                ldsm_x4_t(vf[p], vb + (uint32_t)((krow * AST + p * 16 + no) * 2));
#pragma unroll
            for (int p = 0; p < 4; p++) {
                mma_fp16(o[2 * p],     pa[kk2], vf[p][0], vf[p][1]);
                mma_fp16(o[2 * p + 1], pa[kk2], vf[p][2], vf[p][3]);
            }
        }
        __syncthreads();
    }

    // ---- epilogue -> fp16 ctx ----
    float inv0 = 1.0f / l0, inv1 = 1.0f / l1;
#pragma unroll
    for (int t = 0; t < 8; t++) {
        int d = h * DH + 8 * t + 2 * tg;
        __half2 a = __float22half2_rn(make_float2(o[t][0] * inv0, o[t][1] * inv0));
        __half2 b = __float22half2_rn(make_float2(o[t][2] * inv1, o[t][3] * inv1));
        *(uint32_t*)&ctxf[(size_t)(row0 + g) * DMODEL + d]     = h2u(a);
        *(uint32_t*)&ctxf[(size_t)(row0 + g + 8) * DMODEL + d] = h2u(b);
    }
}

// ============================================================
extern "C" void kernel_launch(void* const* d_in, const int* in_sizes, int n_in,
                              void* d_out, int out_size)
{
    const float* x     = (const float*)d_in[0];
    const float* w_qkv = (const float*)d_in[1];
    const float* b_qkv = (const float*)d_in[2];
    const float* w_out = (const float*)d_in[3];
    const float* b_out = (const float*)d_in[4];
    float* out = (float*)d_out;

    __half *xf, *wqf, *wof, *qkvf, *ctxf;
    cudaGetSymbolAddress((void**)&xf, g_xf);
    cudaGetSymbolAddress((void**)&wqf, g_wqf);
    cudaGetSymbolAddress((void**)&wof, g_wof);
    cudaGetSymbolAddress((void**)&qkvf, g_qkvf);
    cudaGetSymbolAddress((void**)&ctxf, g_ctxf);

    // 0) prepass: fp32 -> fp16
    {
        int n4;
        n4 = SEQ * DMODEL / 4;
        tohalf_kernel<<<(n4 + 255) / 256, 256>>>(x, xf, n4);
        n4 = QKVDIM * DMODEL / 4;
        tohalf_kernel<<<(n4 + 255) / 256, 256>>>(w_qkv, wqf, n4);
        n4 = DMODEL * DMODEL / 4;
        tohalf_kernel<<<(n4 + 255) / 256, 256>>>(w_out, wof, n4);
    }

    // 1) QKV projection -> fp16 qkv
    {
        cudaFuncSetAttribute(gemm_fp16<true>,
                             cudaFuncAttributeMaxDynamicSharedMemorySize, HGEMM_SMEM_BYTES);
        dim3 grid(QKVDIM / 128, SEQ / 128);
        gemm_fp16<true><<<grid, 256, HGEMM_SMEM_BYTES>>>(
            xf, wqf, b_qkv, nullptr, qkvf, SEQ, QKVDIM, DMODEL);
    }

    // 2) flash attention -> fp16 ctx
    {
        cudaFuncSetAttribute(flash_attn_v4,
                             cudaFuncAttributeMaxDynamicSharedMemorySize, ATT_SMEM_BYTES);
        dim3 grid(SEQ / 64, NHEADS);
        flash_attn_v4<<<grid, 128, ATT_SMEM_BYTES>>>(qkvf, ctxf);
    }

    // 3) output projection -> fp32 out
    {
        cudaFuncSetAttribute(gemm_fp16<false>,
                             cudaFuncAttributeMaxDynamicSharedMemorySize, HGEMM_SMEM_BYTES);
        dim3 grid(DMODEL / 128, SEQ / 128);
        gemm_fp16<false><<<grid, 256, HGEMM_SMEM_BYTES>>>(
            ctxf, wof, b_out, out, nullptr, SEQ, DMODEL, DMODEL);
    }
}

// round 9
// speedup vs baseline: 2.6846x; 1.0605x over previous
#include <cuda_runtime.h>
#include <cuda_fp16.h>
#include <cstdint>

#define SEQ     4096
#define DMODEL  1024
#define NHEADS  16
#define DH      64
#define QKVDIM  (3 * DMODEL)

// ---------------- scratch ----------------
__device__ __half g_xf[(size_t)SEQ * DMODEL];
__device__ __half g_wqf[(size_t)QKVDIM * DMODEL];
__device__ __half g_wof[(size_t)DMODEL * DMODEL];
__device__ __half g_qkvf[(size_t)SEQ * QKVDIM];
__device__ __half g_ctxf[(size_t)SEQ * DMODEL];

// ============================================================
// helpers
// ============================================================
__device__ __forceinline__ uint32_t smaddr(const void* p) {
    return static_cast<uint32_t>(__cvta_generic_to_shared(p));
}
__device__ __forceinline__ uint32_t h2u(__half2 v) {
    return *reinterpret_cast<uint32_t*>(&v);
}
__device__ __forceinline__ void ldsm_x4(uint32_t* r, uint32_t addr) {
    asm volatile("ldmatrix.sync.aligned.m8n8.x4.shared.b16 {%0,%1,%2,%3}, [%4];"
                 : "=r"(r[0]), "=r"(r[1]), "=r"(r[2]), "=r"(r[3]) : "r"(addr));
}
__device__ __forceinline__ void ldsm_x4_t(uint32_t* r, uint32_t addr) {
    asm volatile("ldmatrix.sync.aligned.m8n8.x4.trans.shared.b16 {%0,%1,%2,%3}, [%4];"
                 : "=r"(r[0]), "=r"(r[1]), "=r"(r[2]), "=r"(r[3]) : "r"(addr));
}
__device__ __forceinline__ void mma_fp16(float* d, const uint32_t* a, uint32_t b0, uint32_t b1) {
    asm volatile(
        "mma.sync.aligned.m16n8k16.row.col.f32.f16.f16.f32 "
        "{%0,%1,%2,%3}, {%4,%5,%6,%7}, {%8,%9}, {%0,%1,%2,%3};"
        : "+f"(d[0]), "+f"(d[1]), "+f"(d[2]), "+f"(d[3])
        : "r"(a[0]), "r"(a[1]), "r"(a[2]), "r"(a[3]), "r"(b0), "r"(b1));
}
#define CP16(dst, src) asm volatile("cp.async.cg.shared.global [%0], [%1], 16;" :: "r"(dst), "l"(src))
#define CP_COMMIT()    asm volatile("cp.async.commit_group;")
#define CP_WAIT1()     asm volatile("cp.async.wait_group 1;")
#define CP_WAIT0()     asm volatile("cp.async.wait_group 0;")

// ============================================================
// prepass: fp32 -> fp16
// ============================================================
__global__ void tohalf_kernel(const float* __restrict__ in,
                              __half* __restrict__ o, int n4)
{
    int i = blockIdx.x * blockDim.x + threadIdx.x;
    if (i >= n4) return;
    float4 v = ((const float4*)in)[i];
    __half2 a = __float22half2_rn(make_float2(v.x, v.y));
    __half2 b = __float22half2_rn(make_float2(v.z, v.w));
    ((uint2*)o)[i] = make_uint2(h2u(a), h2u(b));
}

// ============================================================
// fp16 GEMM: C[M,N] = A[M,K]*B[N,K]^T + bias, K-step 64.
// ============================================================
#define KST 72
#define HSTAGE (2 * 128 * KST)
#define HGEMM_SMEM_BYTES (2 * HSTAGE * 2)    // 73728

template <bool HALF_OUT>
__global__ __launch_bounds__(256)
void gemm_fp16(const __half* __restrict__ A, const __half* __restrict__ B,
               const float* __restrict__ bias,
               float* __restrict__ Cf, __half* __restrict__ Ch,
               int M, int N, int K)
{
    extern __shared__ __half hsm[];

    const int tid = threadIdx.x;
    const int w = tid >> 5, lane = tid & 31;
    const int wr = w >> 2, wc = w & 3;
    const int g = lane >> 2, tg = lane & 3;
    const int bm = blockIdx.y * 128, bn = blockIdx.x * 128;

    const uint32_t smb = smaddr(hsm);

    float acc[4][4][4];
#pragma unroll
    for (int a = 0; a < 4; a++)
#pragma unroll
        for (int b = 0; b < 4; b++)
#pragma unroll
            for (int c = 0; c < 4; c++) acc[a][b][c] = 0.f;

    auto issue_stage = [&](int kt, int stage) {
        const size_t ko = (size_t)kt * 64;
        uint32_t base = smb + (uint32_t)stage * HSTAGE * 2;
#pragma unroll
        for (int i = 0; i < 4; i++) {
            int idx = tid + i * 256;
            int r = idx >> 3, c = idx & 7;
            uint32_t d = base + (uint32_t)(r * KST + c * 8) * 2;
            CP16(d,                 A + (size_t)(bm + r) * K + ko + c * 8);
            CP16(d + 128 * KST * 2, B + (size_t)(bn + r) * K + ko + c * 8);
        }
    };

    const int nsteps = K >> 6;
    issue_stage(0, 0);
    CP_COMMIT();

    for (int kt = 0; kt < nsteps; kt++) {
        if (kt + 1 < nsteps) {
            issue_stage(kt + 1, (kt + 1) & 1);
            CP_COMMIT();
            CP_WAIT1();
        } else {
            CP_WAIT0();
        }
        __syncthreads();

        uint32_t ab = smb + (uint32_t)(kt & 1) * HSTAGE * 2;
        uint32_t bb = ab + 128 * KST * 2;

#pragma unroll
        for (int kk = 0; kk < 4; kk++) {
            uint32_t fa[4][4];
            {
                int row = wr * 64 + (lane & 15);
                int ko = kk * 16 + (lane >> 4) * 8;
#pragma unroll
                for (int mt = 0; mt < 4; mt++)
                    ldsm_x4(fa[mt], ab + (uint32_t)(((row + mt * 16) * KST + ko) * 2));
            }
            uint32_t fb[2][4];
            {
                int row = wc * 32 + (lane & 7) + ((lane >> 4) << 3);
                int ko = kk * 16 + ((lane >> 3) & 1) * 8;
#pragma unroll
                for (int p = 0; p < 2; p++)
                    ldsm_x4(fb[p], bb + (uint32_t)(((row + p * 16) * KST + ko) * 2));
            }
#pragma unroll
            for (int mt = 0; mt < 4; mt++) {
#pragma unroll
                for (int p = 0; p < 2; p++) {
                    mma_fp16(acc[mt][2 * p],     fa[mt], fb[p][0], fb[p][1]);
                    mma_fp16(acc[mt][2 * p + 1], fa[mt], fb[p][2], fb[p][3]);
                }
            }
        }
        __syncthreads();
    }

#pragma unroll
    for (int mt = 0; mt < 4; mt++) {
        int row = bm + wr * 64 + mt * 16 + g;
#pragma unroll
        for (int nt = 0; nt < 4; nt++) {
            int col = bn + wc * 32 + nt * 8 + 2 * tg;
            float bx = bias[col], by = bias[col + 1];
            float v00 = acc[mt][nt][0] + bx, v01 = acc[mt][nt][1] + by;
            float v10 = acc[mt][nt][2] + bx, v11 = acc[mt][nt][3] + by;
            if (HALF_OUT) {
                __half2 a = __float22half2_rn(make_float2(v00, v01));
                __half2 b = __float22half2_rn(make_float2(v10, v11));
                *(uint32_t*)&Ch[(size_t)row * N + col]       = h2u(a);
                *(uint32_t*)&Ch[(size_t)(row + 8) * N + col] = h2u(b);
            } else {
                *(float2*)&Cf[(size_t)row * N + col]       = make_float2(v00, v01);
                *(float2*)&Cf[(size_t)(row + 8) * N + col] = make_float2(v10, v11);
            }
        }
    }
}

// ============================================================
// Flash attention v5: BN=128 key tiles, exp2-domain softmax,
// tree reductions. BM=64, 128 thr, 3 CTAs/SM.
// ============================================================
#define BN2 128
#define AST 72
#define KV_STAGE (2 * BN2 * AST)
#define ATT_SMEM_BYTES (2 * KV_STAGE * 2)    // 73728

__global__ __launch_bounds__(128, 3)
void flash_attn_v5(const __half* __restrict__ qkvf, __half* __restrict__ ctxf)
{
    extern __shared__ __half sm[];

    const int h = blockIdx.y;
    const int qb = blockIdx.x;
    const int tid = threadIdx.x;
    const int w = tid >> 5, lane = tid & 31;
    const int g = lane >> 2, tg = lane & 3;

    const uint32_t smb = smaddr(sm);

    const size_t koff = DMODEL + (size_t)h * DH;
    const size_t voff = 2 * DMODEL + (size_t)h * DH;

    // ---- Q fragments via direct LDG, pre-scaled by 0.125*log2(e) ----
    const int row0 = qb * 64 + w * 16;
    const __half2 QSC = __float2half2_rn(0.18033688f);
    uint32_t qf[4][4];
#pragma unroll
    for (int kk = 0; kk < 4; kk++) {
        size_t c = (size_t)h * DH + kk * 16 + 2 * tg;
        size_t rA = (size_t)(row0 + g) * QKVDIM + c;
        size_t rB = (size_t)(row0 + g + 8) * QKVDIM + c;
        qf[kk][0] = *(const uint32_t*)&qkvf[rA];
        qf[kk][1] = *(const uint32_t*)&qkvf[rB];
        qf[kk][2] = *(const uint32_t*)&qkvf[rA + 8];
        qf[kk][3] = *(const uint32_t*)&qkvf[rB + 8];
#pragma unroll
        for (int j = 0; j < 4; j++) {
            __half2 q = *reinterpret_cast<__half2*>(&qf[kk][j]);
            q = __hmul2(q, QSC);
            qf[kk][j] = h2u(q);
        }
    }

    auto issue_kv = [&](int kt, int stage) {
        uint32_t base = smb + (uint32_t)(stage * KV_STAGE) * 2;
        size_t rofs = (size_t)kt * BN2 * QKVDIM;
#pragma unroll
        for (int i = 0; i < 8; i++) {
            int idx = tid + i * 128;          // 1024: 128 rows x 8 chunks
            int r = idx >> 3, c = idx & 7;
            uint32_t d = base + (uint32_t)(r * AST + c * 8) * 2;
            size_t srow = rofs + (size_t)r * QKVDIM + c * 8;
            CP16(d,                 qkvf + koff + srow);
            CP16(d + BN2 * AST * 2, qkvf + voff + srow);
        }
    };
    issue_kv(0, 0);
    CP_COMMIT();

    float m0 = -1e30f, m1 = -1e30f, l0 = 0.f, l1 = 0.f;
    float o[8][4];
#pragma unroll
    for (int t = 0; t < 8; t++)
#pragma unroll
        for (int c = 0; c < 4; c++) o[t][c] = 0.f;

    const int NT = SEQ / BN2;    // 32
    for (int kt = 0; kt < NT; kt++) {
        if (kt + 1 < NT) {
            issue_kv(kt + 1, (kt + 1) & 1);
            CP_COMMIT();
            CP_WAIT1();
        } else {
            CP_WAIT0();
        }
        __syncthreads();

        uint32_t kb = smb + (uint32_t)((kt & 1) * KV_STAGE) * 2;
        uint32_t vb = kb + BN2 * AST * 2;

        // ---- S = Q K^T over 128 keys (16 ntiles) ----
        float s[16][4];
#pragma unroll
        for (int t = 0; t < 16; t++)
#pragma unroll
            for (int c = 0; c < 4; c++) s[t][c] = 0.f;

#pragma unroll
        for (int kk = 0; kk < 4; kk++) {
            int nrow = (lane & 7) + ((lane >> 4) << 3);
            int ko = kk * 16 + ((lane >> 3) & 1) * 8;
#pragma unroll
            for (int p = 0; p < 8; p++) {
                uint32_t kf[4];
                ldsm_x4(kf, kb + (uint32_t)(((nrow + p * 16) * AST + ko) * 2));
                mma_fp16(s[2 * p],     qf[kk], kf[0], kf[1]);
                mma_fp16(s[2 * p + 1], qf[kk], kf[2], kf[3]);
            }
        }

        // ---- online softmax (exp2 domain), tree reductions ----
        // row-group 0: cols 0,1 ; row-group 1: cols 2,3
        {
            float r0[8], r1[8];
#pragma unroll
            for (int i = 0; i < 8; i++) {
                r0[i] = fmaxf(fmaxf(s[2 * i][0], s[2 * i][1]),
                              fmaxf(s[2 * i + 1][0], s[2 * i + 1][1]));
                r1[i] = fmaxf(fmaxf(s[2 * i][2], s[2 * i][3]),
                              fmaxf(s[2 * i + 1][2], s[2 * i + 1][3]));
            }
#pragma unroll
            for (int st = 4; st > 0; st >>= 1)
#pragma unroll
                for (int i = 0; i < st; i++) {
                    r0[i] = fmaxf(r0[i], r0[i + st]);
                    r1[i] = fmaxf(r1[i], r1[i + st]);
                }
            float bm0 = r0[0], bm1 = r1[0];
            bm0 = fmaxf(bm0, __shfl_xor_sync(0xffffffffu, bm0, 1));
            bm1 = fmaxf(bm1, __shfl_xor_sync(0xffffffffu, bm1, 1));
            bm0 = fmaxf(bm0, __shfl_xor_sync(0xffffffffu, bm0, 2));
            bm1 = fmaxf(bm1, __shfl_xor_sync(0xffffffffu, bm1, 2));

            float mn0 = fmaxf(m0, bm0), mn1 = fmaxf(m1, bm1);
            float c0 = exp2f(m0 - mn0), c1 = exp2f(m1 - mn1);

#pragma unroll
            for (int t = 0; t < 16; t++) {
                s[t][0] = exp2f(s[t][0] - mn0);
                s[t][1] = exp2f(s[t][1] - mn0);
                s[t][2] = exp2f(s[t][2] - mn1);
                s[t][3] = exp2f(s[t][3] - mn1);
            }
#pragma unroll
            for (int i = 0; i < 8; i++) {
                r0[i] = (s[2 * i][0] + s[2 * i][1]) + (s[2 * i + 1][0] + s[2 * i + 1][1]);
                r1[i] = (s[2 * i][2] + s[2 * i][3]) + (s[2 * i + 1][2] + s[2 * i + 1][3]);
            }
#pragma unroll
            for (int st = 4; st > 0; st >>= 1)
#pragma unroll
                for (int i = 0; i < st; i++) {
                    r0[i] += r0[i + st];
                    r1[i] += r1[i + st];
                }
            float sum0 = r0[0], sum1 = r1[0];
            sum0 += __shfl_xor_sync(0xffffffffu, sum0, 1);
            sum1 += __shfl_xor_sync(0xffffffffu, sum1, 1);
            sum0 += __shfl_xor_sync(0xffffffffu, sum0, 2);
            sum1 += __shfl_xor_sync(0xffffffffu, sum1, 2);

            l0 = l0 * c0 + sum0; m0 = mn0;
            l1 = l1 * c1 + sum1; m1 = mn1;
#pragma unroll
            for (int t = 0; t < 8; t++) {
                o[t][0] *= c0; o[t][1] *= c0;
                o[t][2] *= c1; o[t][3] *= c1;
            }
        }

        // ---- O += P V (pack P on the fly) ----
#pragma unroll
        for (int kk2 = 0; kk2 < 8; kk2++) {
            uint32_t pa[4];
            pa[0] = h2u(__float22half2_rn(make_float2(s[2 * kk2][0],     s[2 * kk2][1])));
            pa[1] = h2u(__float22half2_rn(make_float2(s[2 * kk2][2],     s[2 * kk2][3])));
            pa[2] = h2u(__float22half2_rn(make_float2(s[2 * kk2 + 1][0], s[2 * kk2 + 1][1])));
            pa[3] = h2u(__float22half2_rn(make_float2(s[2 * kk2 + 1][2], s[2 * kk2 + 1][3])));

            int krow = kk2 * 16 + (lane & 15);
            int no = (lane >> 4) * 8;
#pragma unroll
            for (int p = 0; p < 4; p++) {
                uint32_t vf[4];
                ldsm_x4_t(vf, vb + (uint32_t)((krow * AST + p * 16 + no) * 2));
                mma_fp16(o[2 * p],     pa, vf[0], vf[1]);
                mma_fp16(o[2 * p + 1], pa, vf[2], vf[3]);
            }
        }
        __syncthreads();
    }

    // ---- epilogue -> fp16 ctx ----
    float inv0 = 1.0f / l0, inv1 = 1.0f / l1;
#pragma unroll
    for (int t = 0; t < 8; t++) {
        int d = h * DH + 8 * t + 2 * tg;
        __half2 a = __float22half2_rn(make_float2(o[t][0] * inv0, o[t][1] * inv0));
        __half2 b = __float22half2_rn(make_float2(o[t][2] * inv1, o[t][3] * inv1));
        *(uint32_t*)&ctxf[(size_t)(row0 + g) * DMODEL + d]     = h2u(a);
        *(uint32_t*)&ctxf[(size_t)(row0 + g + 8) * DMODEL + d] = h2u(b);
    }
}

// ============================================================
extern "C" void kernel_launch(void* const* d_in, const int* in_sizes, int n_in,
                              void* d_out, int out_size)
{
    const float* x     = (const float*)d_in[0];
    const float* w_qkv = (const float*)d_in[1];
    const float* b_qkv = (const float*)d_in[2];
    const float* w_out = (const float*)d_in[3];
    const float* b_out = (const float*)d_in[4];
    float* out = (float*)d_out;

    __half *xf, *wqf, *wof, *qkvf, *ctxf;
    cudaGetSymbolAddress((void**)&xf, g_xf);
    cudaGetSymbolAddress((void**)&wqf, g_wqf);
    cudaGetSymbolAddress((void**)&wof, g_wof);
    cudaGetSymbolAddress((void**)&qkvf, g_qkvf);
    cudaGetSymbolAddress((void**)&ctxf, g_ctxf);

    // 0) prepass: fp32 -> fp16
    {
        int n4;
        n4 = SEQ * DMODEL / 4;
        tohalf_kernel<<<(n4 + 255) / 256, 256>>>(x, xf, n4);
        n4 = QKVDIM * DMODEL / 4;
        tohalf_kernel<<<(n4 + 255) / 256, 256>>>(w_qkv, wqf, n4);
        n4 = DMODEL * DMODEL / 4;
        tohalf_kernel<<<(n4 + 255) / 256, 256>>>(w_out, wof, n4);
    }

    // 1) QKV projection -> fp16 qkv
    {
        cudaFuncSetAttribute(gemm_fp16<true>,
                             cudaFuncAttributeMaxDynamicSharedMemorySize, HGEMM_SMEM_BYTES);
        dim3 grid(QKVDIM / 128, SEQ / 128);
        gemm_fp16<true><<<grid, 256, HGEMM_SMEM_BYTES>>>(
            xf, wqf, b_qkv, nullptr, qkvf, SEQ, QKVDIM, DMODEL);
    }

    // 2) flash attention -> fp16 ctx
    {
        cudaFuncSetAttribute(flash_attn_v5,
                             cudaFuncAttributeMaxDynamicSharedMemorySize, ATT_SMEM_BYTES);
        dim3 grid(SEQ / 64, NHEADS);
        flash_attn_v5<<<grid, 128, ATT_SMEM_BYTES>>>(qkvf, ctxf);
    }

    // 3) output projection -> fp32 out
    {
        cudaFuncSetAttribute(gemm_fp16<false>,
                             cudaFuncAttributeMaxDynamicSharedMemorySize, HGEMM_SMEM_BYTES);
        dim3 grid(DMODEL / 128, SEQ / 128);
        gemm_fp16<false><<<grid, 256, HGEMM_SMEM_BYTES>>>(
            ctxf, wof, b_out, out, nullptr, SEQ, DMODEL, DMODEL);
    }
}

// round 10
// speedup vs baseline: 2.6874x; 1.0011x over previous
#include <cuda_runtime.h>
#include <cuda_fp16.h>
#include <cstdint>

#define SEQ     4096
#define DMODEL  1024
#define NHEADS  16
#define DH      64
#define QKVDIM  (3 * DMODEL)

// ---------------- scratch ----------------
__device__ __half g_xf[(size_t)SEQ * DMODEL];
__device__ __half g_wqf[(size_t)QKVDIM * DMODEL];
__device__ __half g_wof[(size_t)DMODEL * DMODEL];
__device__ __half g_qkvf[(size_t)SEQ * QKVDIM];
__device__ __half g_ctxf[(size_t)SEQ * DMODEL];

// ============================================================
// helpers
// ============================================================
__device__ __forceinline__ uint32_t smaddr(const void* p) {
    return static_cast<uint32_t>(__cvta_generic_to_shared(p));
}
__device__ __forceinline__ uint32_t h2u(__half2 v) {
    return *reinterpret_cast<uint32_t*>(&v);
}
__device__ __forceinline__ float ex2(float x) {
    float y;
    asm("ex2.approx.f32 %0, %1;" : "=f"(y) : "f"(x));
    return y;
}
__device__ __forceinline__ float frcp(float x) {
    float y;
    asm("rcp.approx.f32 %0, %1;" : "=f"(y) : "f"(x));
    return y;
}
__device__ __forceinline__ void ldsm_x4(uint32_t* r, uint32_t addr) {
    asm volatile("ldmatrix.sync.aligned.m8n8.x4.shared.b16 {%0,%1,%2,%3}, [%4];"
                 : "=r"(r[0]), "=r"(r[1]), "=r"(r[2]), "=r"(r[3]) : "r"(addr));
}
__device__ __forceinline__ void ldsm_x4_t(uint32_t* r, uint32_t addr) {
    asm volatile("ldmatrix.sync.aligned.m8n8.x4.trans.shared.b16 {%0,%1,%2,%3}, [%4];"
                 : "=r"(r[0]), "=r"(r[1]), "=r"(r[2]), "=r"(r[3]) : "r"(addr));
}
__device__ __forceinline__ void mma_fp16(float* d, const uint32_t* a, uint32_t b0, uint32_t b1) {
    asm volatile(
        "mma.sync.aligned.m16n8k16.row.col.f32.f16.f16.f32 "
        "{%0,%1,%2,%3}, {%4,%5,%6,%7}, {%8,%9}, {%0,%1,%2,%3};"
        : "+f"(d[0]), "+f"(d[1]), "+f"(d[2]), "+f"(d[3])
        : "r"(a[0]), "r"(a[1]), "r"(a[2]), "r"(a[3]), "r"(b0), "r"(b1));
}
#define CP16(dst, src) asm volatile("cp.async.cg.shared.global [%0], [%1], 16;" :: "r"(dst), "l"(src))
#define CP_COMMIT()    asm volatile("cp.async.commit_group;")
#define CP_WAIT1()     asm volatile("cp.async.wait_group 1;")
#define CP_WAIT0()     asm volatile("cp.async.wait_group 0;")

// ============================================================
// prepass: fp32 -> fp16
// ============================================================
__global__ void tohalf_kernel(const float* __restrict__ in,
                              __half* __restrict__ o, int n4)
{
    int i = blockIdx.x * blockDim.x + threadIdx.x;
    if (i >= n4) return;
    float4 v = ((const float4*)in)[i];
    __half2 a = __float22half2_rn(make_float2(v.x, v.y));
    __half2 b = __float22half2_rn(make_float2(v.z, v.w));
    ((uint2*)o)[i] = make_uint2(h2u(a), h2u(b));
}

// ============================================================
// fp16 GEMM: C[M,N] = A[M,K]*B[N,K]^T + bias, K-step 64.
// ============================================================
#define KST 72
#define HSTAGE (2 * 128 * KST)
#define HGEMM_SMEM_BYTES (2 * HSTAGE * 2)    // 73728

template <bool HALF_OUT>
__global__ __launch_bounds__(256)
void gemm_fp16(const __half* __restrict__ A, const __half* __restrict__ B,
               const float* __restrict__ bias,
               float* __restrict__ Cf, __half* __restrict__ Ch,
               int M, int N, int K)
{
    extern __shared__ __half hsm[];

    const int tid = threadIdx.x;
    const int w = tid >> 5, lane = tid & 31;
    const int wr = w >> 2, wc = w & 3;
    const int g = lane >> 2, tg = lane & 3;
    const int bm = blockIdx.y * 128, bn = blockIdx.x * 128;

    const uint32_t smb = smaddr(hsm);

    float acc[4][4][4];
#pragma unroll
    for (int a = 0; a < 4; a++)
#pragma unroll
        for (int b = 0; b < 4; b++)
#pragma unroll
            for (int c = 0; c < 4; c++) acc[a][b][c] = 0.f;

    auto issue_stage = [&](int kt, int stage) {
        const size_t ko = (size_t)kt * 64;
        uint32_t base = smb + (uint32_t)stage * HSTAGE * 2;
#pragma unroll
        for (int i = 0; i < 4; i++) {
            int idx = tid + i * 256;
            int r = idx >> 3, c = idx & 7;
            uint32_t d = base + (uint32_t)(r * KST + c * 8) * 2;
            CP16(d,                 A + (size_t)(bm + r) * K + ko + c * 8);
            CP16(d + 128 * KST * 2, B + (size_t)(bn + r) * K + ko + c * 8);
        }
    };

    const int nsteps = K >> 6;
    issue_stage(0, 0);
    CP_COMMIT();

    for (int kt = 0; kt < nsteps; kt++) {
        if (kt + 1 < nsteps) {
            issue_stage(kt + 1, (kt + 1) & 1);
            CP_COMMIT();
            CP_WAIT1();
        } else {
            CP_WAIT0();
        }
        __syncthreads();

        uint32_t ab = smb + (uint32_t)(kt & 1) * HSTAGE * 2;
        uint32_t bb = ab + 128 * KST * 2;

#pragma unroll
        for (int kk = 0; kk < 4; kk++) {
            uint32_t fa[4][4];
            {
                int row = wr * 64 + (lane & 15);
                int ko = kk * 16 + (lane >> 4) * 8;
#pragma unroll
                for (int mt = 0; mt < 4; mt++)
                    ldsm_x4(fa[mt], ab + (uint32_t)(((row + mt * 16) * KST + ko) * 2));
            }
            uint32_t fb[2][4];
            {
                int row = wc * 32 + (lane & 7) + ((lane >> 4) << 3);
                int ko = kk * 16 + ((lane >> 3) & 1) * 8;
#pragma unroll
                for (int p = 0; p < 2; p++)
                    ldsm_x4(fb[p], bb + (uint32_t)(((row + p * 16) * KST + ko) * 2));
            }
#pragma unroll
            for (int mt = 0; mt < 4; mt++) {
#pragma unroll
                for (int p = 0; p < 2; p++) {
                    mma_fp16(acc[mt][2 * p],     fa[mt], fb[p][0], fb[p][1]);
                    mma_fp16(acc[mt][2 * p + 1], fa[mt], fb[p][2], fb[p][3]);
                }
            }
        }
        __syncthreads();
    }

#pragma unroll
    for (int mt = 0; mt < 4; mt++) {
        int row = bm + wr * 64 + mt * 16 + g;
#pragma unroll
        for (int nt = 0; nt < 4; nt++) {
            int col = bn + wc * 32 + nt * 8 + 2 * tg;
            float bx = bias[col], by = bias[col + 1];
            float v00 = acc[mt][nt][0] + bx, v01 = acc[mt][nt][1] + by;
            float v10 = acc[mt][nt][2] + bx, v11 = acc[mt][nt][3] + by;
            if (HALF_OUT) {
                __half2 a = __float22half2_rn(make_float2(v00, v01));
                __half2 b = __float22half2_rn(make_float2(v10, v11));
                *(uint32_t*)&Ch[(size_t)row * N + col]       = h2u(a);
                *(uint32_t*)&Ch[(size_t)(row + 8) * N + col] = h2u(b);
            } else {
                *(float2*)&Cf[(size_t)row * N + col]       = make_float2(v00, v01);
                *(float2*)&Cf[(size_t)(row + 8) * N + col] = make_float2(v10, v11);
            }
        }
    }
}

// ============================================================
// Flash attention v6: BN=128, exp2-domain softmax w/ raw MUFU EX2,
// tree reductions. BM=64, 128 thr, 3 CTAs/SM.
// ============================================================
#define BN2 128
#define AST 72
#define KV_STAGE (2 * BN2 * AST)
#define ATT_SMEM_BYTES (2 * KV_STAGE * 2)    // 73728

__global__ __launch_bounds__(128, 3)
void flash_attn_v6(const __half* __restrict__ qkvf, __half* __restrict__ ctxf)
{
    extern __shared__ __half sm[];

    const int h = blockIdx.y;
    const int qb = blockIdx.x;
    const int tid = threadIdx.x;
    const int w = tid >> 5, lane = tid & 31;
    const int g = lane >> 2, tg = lane & 3;

    const uint32_t smb = smaddr(sm);

    const size_t koff = DMODEL + (size_t)h * DH;
    const size_t voff = 2 * DMODEL + (size_t)h * DH;

    // ---- Q fragments via direct LDG, pre-scaled by 0.125*log2(e) ----
    const int row0 = qb * 64 + w * 16;
    const __half2 QSC = __float2half2_rn(0.18033688f);
    uint32_t qf[4][4];
#pragma unroll
    for (int kk = 0; kk < 4; kk++) {
        size_t c = (size_t)h * DH + kk * 16 + 2 * tg;
        size_t rA = (size_t)(row0 + g) * QKVDIM + c;
        size_t rB = (size_t)(row0 + g + 8) * QKVDIM + c;
        qf[kk][0] = *(const uint32_t*)&qkvf[rA];
        qf[kk][1] = *(const uint32_t*)&qkvf[rB];
        qf[kk][2] = *(const uint32_t*)&qkvf[rA + 8];
        qf[kk][3] = *(const uint32_t*)&qkvf[rB + 8];
#pragma unroll
        for (int j = 0; j < 4; j++) {
            __half2 q = *reinterpret_cast<__half2*>(&qf[kk][j]);
            q = __hmul2(q, QSC);
            qf[kk][j] = h2u(q);
        }
    }

    auto issue_kv = [&](int kt, int stage) {
        uint32_t base = smb + (uint32_t)(stage * KV_STAGE) * 2;
        size_t rofs = (size_t)kt * BN2 * QKVDIM;
#pragma unroll
        for (int i = 0; i < 8; i++) {
            int idx = tid + i * 128;
            int r = idx >> 3, c = idx & 7;
            uint32_t d = base + (uint32_t)(r * AST + c * 8) * 2;
            size_t srow = rofs + (size_t)r * QKVDIM + c * 8;
            CP16(d,                 qkvf + koff + srow);
            CP16(d + BN2 * AST * 2, qkvf + voff + srow);
        }
    };
    issue_kv(0, 0);
    CP_COMMIT();

    float m0 = -1e30f, m1 = -1e30f, l0 = 0.f, l1 = 0.f;
    float o[8][4];
#pragma unroll
    for (int t = 0; t < 8; t++)
#pragma unroll
        for (int c = 0; c < 4; c++) o[t][c] = 0.f;

    const int NT = SEQ / BN2;    // 32
    for (int kt = 0; kt < NT; kt++) {
        if (kt + 1 < NT) {
            issue_kv(kt + 1, (kt + 1) & 1);
            CP_COMMIT();
            CP_WAIT1();
        } else {
            CP_WAIT0();
        }
        __syncthreads();

        uint32_t kb = smb + (uint32_t)((kt & 1) * KV_STAGE) * 2;
        uint32_t vb = kb + BN2 * AST * 2;

        // ---- S = Q K^T over 128 keys (16 ntiles) ----
        float s[16][4];
#pragma unroll
        for (int t = 0; t < 16; t++)
#pragma unroll
            for (int c = 0; c < 4; c++) s[t][c] = 0.f;

#pragma unroll
        for (int kk = 0; kk < 4; kk++) {
            int nrow = (lane & 7) + ((lane >> 4) << 3);
            int ko = kk * 16 + ((lane >> 3) & 1) * 8;
#pragma unroll
            for (int p = 0; p < 8; p++) {
                uint32_t kf[4];
                ldsm_x4(kf, kb + (uint32_t)(((nrow + p * 16) * AST + ko) * 2));
                mma_fp16(s[2 * p],     qf[kk], kf[0], kf[1]);
                mma_fp16(s[2 * p + 1], qf[kk], kf[2], kf[3]);
            }
        }

        // ---- online softmax (exp2 domain, raw MUFU), tree reductions ----
        {
            float r0[8], r1[8];
#pragma unroll
            for (int i = 0; i < 8; i++) {
                r0[i] = fmaxf(fmaxf(s[2 * i][0], s[2 * i][1]),
                              fmaxf(s[2 * i + 1][0], s[2 * i + 1][1]));
                r1[i] = fmaxf(fmaxf(s[2 * i][2], s[2 * i][3]),
                              fmaxf(s[2 * i + 1][2], s[2 * i + 1][3]));
            }
#pragma unroll
            for (int st = 4; st > 0; st >>= 1)
#pragma unroll
                for (int i = 0; i < st; i++) {
                    r0[i] = fmaxf(r0[i], r0[i + st]);
                    r1[i] = fmaxf(r1[i], r1[i + st]);
                }
            float bm0 = r0[0], bm1 = r1[0];
            bm0 = fmaxf(bm0, __shfl_xor_sync(0xffffffffu, bm0, 1));
            bm1 = fmaxf(bm1, __shfl_xor_sync(0xffffffffu, bm1, 1));
            bm0 = fmaxf(bm0, __shfl_xor_sync(0xffffffffu, bm0, 2));
            bm1 = fmaxf(bm1, __shfl_xor_sync(0xffffffffu, bm1, 2));

            float mn0 = fmaxf(m0, bm0), mn1 = fmaxf(m1, bm1);
            float c0 = ex2(m0 - mn0), c1 = ex2(m1 - mn1);

#pragma unroll
            for (int t = 0; t < 16; t++) {
                s[t][0] = ex2(s[t][0] - mn0);
                s[t][1] = ex2(s[t][1] - mn0);
                s[t][2] = ex2(s[t][2] - mn1);
                s[t][3] = ex2(s[t][3] - mn1);
            }
#pragma unroll
            for (int i = 0; i < 8; i++) {
                r0[i] = (s[2 * i][0] + s[2 * i][1]) + (s[2 * i + 1][0] + s[2 * i + 1][1]);
                r1[i] = (s[2 * i][2] + s[2 * i][3]) + (s[2 * i + 1][2] + s[2 * i + 1][3]);
            }
#pragma unroll
            for (int st = 4; st > 0; st >>= 1)
#pragma unroll
                for (int i = 0; i < st; i++) {
                    r0[i] += r0[i + st];
                    r1[i] += r1[i + st];
                }
            float sum0 = r0[0], sum1 = r1[0];
            sum0 += __shfl_xor_sync(0xffffffffu, sum0, 1);
            sum1 += __shfl_xor_sync(0xffffffffu, sum1, 1);
            sum0 += __shfl_xor_sync(0xffffffffu, sum0, 2);
            sum1 += __shfl_xor_sync(0xffffffffu, sum1, 2);

            l0 = l0 * c0 + sum0; m0 = mn0;
            l1 = l1 * c1 + sum1; m1 = mn1;
#pragma unroll
            for (int t = 0; t < 8; t++) {
                o[t][0] *= c0; o[t][1] *= c0;
                o[t][2] *= c1; o[t][3] *= c1;
            }
        }

        // ---- O += P V (pack P on the fly) ----
#pragma unroll
        for (int kk2 = 0; kk2 < 8; kk2++) {
            uint32_t pa[4];
            pa[0] = h2u(__float22half2_rn(make_float2(s[2 * kk2][0],     s[2 * kk2][1])));
            pa[1] = h2u(__float22half2_rn(make_float2(s[2 * kk2][2],     s[2 * kk2][3])));
            pa[2] = h2u(__float22half2_rn(make_float2(s[2 * kk2 + 1][0], s[2 * kk2 + 1][1])));
            pa[3] = h2u(__float22half2_rn(make_float2(s[2 * kk2 + 1][2], s[2 * kk2 + 1][3])));

            int krow = kk2 * 16 + (lane & 15);
            int no = (lane >> 4) * 8;
#pragma unroll
            for (int p = 0; p < 4; p++) {
                uint32_t vf[4];
                ldsm_x4_t(vf, vb + (uint32_t)((krow * AST + p * 16 + no) * 2));
                mma_fp16(o[2 * p],     pa, vf[0], vf[1]);
                mma_fp16(o[2 * p + 1], pa, vf[2], vf[3]);
            }
        }
        __syncthreads();
    }

    // ---- epilogue -> fp16 ctx ----
    float inv0 = frcp(l0), inv1 = frcp(l1);
#pragma unroll
    for (int t = 0; t < 8; t++) {
        int d = h * DH + 8 * t + 2 * tg;
        __half2 a = __float22half2_rn(make_float2(o[t][0] * inv0, o[t][1] * inv0));
        __half2 b = __float22half2_rn(make_float2(o[t][2] * inv1, o[t][3] * inv1));
        *(uint32_t*)&ctxf[(size_t)(row0 + g) * DMODEL + d]     = h2u(a);
        *(uint32_t*)&ctxf[(size_t)(row0 + g + 8) * DMODEL + d] = h2u(b);
    }
}

// ============================================================
extern "C" void kernel_launch(void* const* d_in, const int* in_sizes, int n_in,
                              void* d_out, int out_size)
{
    const float* x     = (const float*)d_in[0];
    const float* w_qkv = (const float*)d_in[1];
    const float* b_qkv = (const float*)d_in[2];
    const float* w_out = (const float*)d_in[3];
    const float* b_out = (const float*)d_in[4];
    float* out = (float*)d_out;

    __half *xf, *wqf, *wof, *qkvf, *ctxf;
    cudaGetSymbolAddress((void**)&xf, g_xf);
    cudaGetSymbolAddress((void**)&wqf, g_wqf);
    cudaGetSymbolAddress((void**)&wof, g_wof);
    cudaGetSymbolAddress((void**)&qkvf, g_qkvf);
    cudaGetSymbolAddress((void**)&ctxf, g_ctxf);

    // 0) prepass: fp32 -> fp16
    {
        int n4;
        n4 = SEQ * DMODEL / 4;
        tohalf_kernel<<<(n4 + 255) / 256, 256>>>(x, xf, n4);
        n4 = QKVDIM * DMODEL / 4;
        tohalf_kernel<<<(n4 + 255) / 256, 256>>>(w_qkv, wqf, n4);
        n4 = DMODEL * DMODEL / 4;
        tohalf_kernel<<<(n4 + 255) / 256, 256>>>(w_out, wof, n4);
    }

    // 1) QKV projection -> fp16 qkv
    {
        cudaFuncSetAttribute(gemm_fp16<true>,
                             cudaFuncAttributeMaxDynamicSharedMemorySize, HGEMM_SMEM_BYTES);
        dim3 grid(QKVDIM / 128, SEQ / 128);
        gemm_fp16<true><<<grid, 256, HGEMM_SMEM_BYTES>>>(
            xf, wqf, b_qkv, nullptr, qkvf, SEQ, QKVDIM, DMODEL);
    }

    // 2) flash attention -> fp16 ctx
    {
        cudaFuncSetAttribute(flash_attn_v6,
                             cudaFuncAttributeMaxDynamicSharedMemorySize, ATT_SMEM_BYTES);
        dim3 grid(SEQ / 64, NHEADS);
        flash_attn_v6<<<grid, 128, ATT_SMEM_BYTES>>>(qkvf, ctxf);
    }

    // 3) output projection -> fp32 out
    {
        cudaFuncSetAttribute(gemm_fp16<false>,
                             cudaFuncAttributeMaxDynamicSharedMemorySize, HGEMM_SMEM_BYTES);
        dim3 grid(DMODEL / 128, SEQ / 128);
        gemm_fp16<false><<<grid, 256, HGEMM_SMEM_BYTES>>>(
            ctxf, wof, b_out, out, nullptr, SEQ, DMODEL, DMODEL);
    }
}